// round 11
// baseline (speedup 1.0000x reference)
#include <cuda_runtime.h>
#include <cuda_bf16.h>
#include <math.h>
#include <stdint.h>

// ---------------- problem constants ----------------
#define G_  100        // B*S graphs
#define N_  2500       // nodes per graph
#define E_  7500       // edges per graph
#define TOT_NODES 250000
#define TOT_EDGES 750000
#define T_  52         // sequence length (S+2)
#define D_  32         // d_model
#define NB_ 104        // transformer blocks (tokens)
#define NT_ 3907       // ceil(250000/64) mma tiles

// ---------------- scratch (static, allocation-free) ----------------
__device__ float g_h1[TOT_NODES * 128];       // 128 MB
__device__ float g_h1a[TOT_NODES * 128];      // 128 MB (edge-aggregated h1)
__device__ float g_dinv[TOT_NODES];
__device__ int   g_off[G_*(N_+1)];
__device__ int   g_rows[TOT_EDGES];
__device__ int   g_pool[G_*256];
__device__ float g_xseq[T_*2*D_];             // [t][b][d]
__device__ float g_qkvbuf[2][NB_*96];
__device__ int   g_bar_cnt;
__device__ volatile int g_bar_gen;
// bf16 hi/lo images of W_g2^T as [n][k], row stride 136 bf16 (68 words)
__device__ __align__(16) unsigned char g_wimg_hi[69632];
__device__ __align__(16) unsigned char g_wimg_lo[69632];

// ---------------- helpers ----------------
__device__ __forceinline__ float2 ffma2(float2 a, float2 b, float2 c) {
    union U { float2 f; unsigned long long u; } ua, ub, uc;
    ua.f = a; ub.f = b; uc.f = c;
    asm("fma.rn.f32x2 %0, %1, %2, %3;" : "=l"(uc.u) : "l"(ua.u), "l"(ub.u), "l"(uc.u));
    return uc.f;
}

__device__ __forceinline__ float warp_sum(float v) {
#pragma unroll
    for (int o = 16; o; o >>= 1) v += __shfl_xor_sync(0xffffffffu, v, o);
    return v;
}
__device__ __forceinline__ float warp_max(float v) {
#pragma unroll
    for (int o = 16; o; o >>= 1) v = fmaxf(v, __shfl_xor_sync(0xffffffffu, v, o));
    return v;
}

__device__ __forceinline__ float leaky(float x) {
    return x >= 0.0f ? x : 0.15f * x;
}

__device__ __forceinline__ int fkey(float f) {
    int i = __float_as_int(f);
    return i >= 0 ? i : (i ^ 0x7FFFFFFF);
}
__device__ __forceinline__ float fdec(int k) {
    return __int_as_float(k >= 0 ? k : (k ^ 0x7FFFFFFF));
}

// mma.sync m16n8k16 bf16 * bf16 -> f32 (baseline PTX; valid on sm_100 target)
__device__ __forceinline__ void mma_bf16(float* c, const uint32_t* a,
                                         uint32_t b0, uint32_t b1) {
    asm volatile(
        "mma.sync.aligned.m16n8k16.row.col.f32.bf16.bf16.f32 "
        "{%0,%1,%2,%3}, {%4,%5,%6,%7}, {%8,%9}, {%0,%1,%2,%3};"
        : "+f"(c[0]), "+f"(c[1]), "+f"(c[2]), "+f"(c[3])
        : "r"(a[0]), "r"(a[1]), "r"(a[2]), "r"(a[3]), "r"(b0), "r"(b1));
}

// ---------------- fused graph prep (+ W_g2 bf16 image build) ----------------
__global__ __launch_bounds__(256) void k_prep(const int* __restrict__ edge,
                                              const float* __restrict__ W_g2) {
    __shared__ int cnt[N_];
    __shared__ int cur[N_];
    __shared__ int sm[256];
    int g = blockIdx.x;
    int t = threadIdx.x;
    for (int i = t; i < N_; i += 256) cnt[i] = 0;
    __syncthreads();

    const int2* eg = (const int2*)edge + (size_t)g * E_;
    for (int i = t; i < E_; i += 256) {
        int2 rc = eg[i];
        atomicAdd(&cnt[rc.y], 1);
    }
    __syncthreads();

    int base = t * 10;
    int loc[10];
    int s = 0;
    if (base < N_) {
#pragma unroll
        for (int i = 0; i < 10; i++) { loc[i] = cnt[base + i]; s += loc[i]; }
    }
    sm[t] = s;
    __syncthreads();
    for (int o = 1; o < 256; o <<= 1) {
        int vv = (t >= o) ? sm[t - o] : 0;
        __syncthreads();
        sm[t] += vv;
        __syncthreads();
    }
    int excl = sm[t] - s;
    if (base < N_) {
        int off = excl;
#pragma unroll
        for (int i = 0; i < 10; i++) {
            g_off[g*(N_+1) + base + i] = off;
            cur[base + i] = off;
            g_dinv[g*N_ + base + i] = rsqrtf((float)loc[i] + 1.0f);
            off += loc[i];
        }
    }
    if (t == 255) g_off[g*(N_+1) + N_] = sm[255];
    __syncthreads();

    for (int i = t; i < E_; i += 256) {
        int2 rc = eg[i];
        int pos = atomicAdd(&cur[rc.y], 1);
        g_rows[(size_t)g*E_ + pos] = rc.x;
    }

    g_pool[g*256 + t] = 0x80000000;
    if (g == 0 && t == 0) { g_bar_cnt = 0; g_bar_gen = 0; }

    // W image: B[n][k] = W_g2[k][n] as bf16 hi/lo, row stride 136 bf16
    for (int idx = g*256 + t; idx < 32768; idx += G_*256) {
        int k = idx >> 8, n = idx & 255;
        float w = W_g2[k*256 + n];
        __nv_bfloat16 hi = __float2bfloat16(w);
        __nv_bfloat16 lo = __float2bfloat16(w - __bfloat162float(hi));
        ((unsigned short*)g_wimg_hi)[n*136 + k] = __bfloat16_as_ushort(hi);
        ((unsigned short*)g_wimg_lo)[n*136 + k] = __bfloat16_as_ushort(lo);
    }
}

// ---------------- fused GCN layer 1: embed + aggregate + GEMM(64->128) ----------------
#define CAP1 320
__global__ __launch_bounds__(128) void k_agg_gemm1(
        const float* __restrict__ v, const float* __restrict__ W_emb,
        const float* __restrict__ b_emb, const float* __restrict__ W_g1,
        const float* __restrict__ b_g1) {
    __shared__ __align__(16) float As[64*56];
    __shared__ __align__(16) float4 ed_s[CAP1];
    __shared__ int   off_s[51];
    __shared__ float dnode[50];
    __shared__ float vself[50*3];
    int n0 = blockIdx.x * 50;
    int g = n0 / N_;
    int lnbase = n0 - g * N_;
    int t  = threadIdx.x;

    const float* dv = g_dinv + g*N_;
    const float* vg = v + (size_t)g * N_ * 3;
    if (t < 51) off_s[t] = g_off[g*(N_+1) + lnbase + t];
    if (t < 50) dnode[t] = dv[lnbase + t];
    for (int idx = t; idx < 150; idx += 128) vself[idx] = vg[(size_t)lnbase*3 + idx];
    __syncthreads();
    int e0 = off_s[0];
    int ecnt = off_s[50] - e0;
    const int* rowsg = g_rows + g*E_ + e0;
    for (int i = t; i < ecnt && i < CAP1; i += 128) {
        int r = rowsg[i];
        const float* vp = vg + (size_t)r*3;
        ed_s[i] = make_float4(vp[0], vp[1], vp[2], dv[r]);
    }
    __syncthreads();

    {
        int c = t & 63;
        int msub = t >> 6;
        float we0 = __ldg(W_emb + c), we1 = __ldg(W_emb + 64 + c);
        float we2 = __ldg(W_emb + 128 + c), be = __ldg(b_emb + c);
#pragma unroll 1
        for (int p = 0; p < 25; p++) {
            int m = p*2 + msub;
            float di = dnode[m];
            float xv = fmaxf(fmaf(vself[m*3+2], we2,
                         fmaf(vself[m*3+1], we1, fmaf(vself[m*3], we0, be))), 0.f);
            float acc = di * di * xv;
            int o0 = off_s[m] - e0, o1 = off_s[m+1] - e0;
            for (int e = o0; e < o1; e++) {
                float4 ed;
                if (e < CAP1) ed = ed_s[e];
                else {
                    int r = rowsg[e];
                    const float* vq = vg + (size_t)r*3;
                    ed = make_float4(vq[0], vq[1], vq[2], dv[r]);
                }
                float xn = fmaxf(fmaf(ed.z, we2, fmaf(ed.y, we1, fmaf(ed.x, we0, be))), 0.f);
                acc = fmaf(di * ed.w, xn, acc);
            }
            As[c*56 + m] = acc;
        }
    }
    __syncthreads();

    {
        int c4 = (t & 31) * 4;
        int mh = t >> 5;
        int mb = mh * 12;
        bool extra = (mh == 3);
        float2 acc[4][7];
#pragma unroll
        for (int j = 0; j < 4; j++)
#pragma unroll
            for (int q = 0; q < 7; q++) acc[j][q] = make_float2(0.f, 0.f);

        const float* Wp = W_g1 + c4;
#pragma unroll 2
        for (int k = 0; k < 64; k++) {
            float4 wv = __ldg((const float4*)(Wp + k*128));
            const float* arow = As + k*56 + mb;
            float4 a0 = *(const float4*)(arow);
            float4 a1 = *(const float4*)(arow + 4);
            float4 a2 = *(const float4*)(arow + 8);
            float wj[4] = {wv.x, wv.y, wv.z, wv.w};
#pragma unroll
            for (int j = 0; j < 4; j++) {
                float2 wp = make_float2(wj[j], wj[j]);
                acc[j][0] = ffma2(make_float2(a0.x, a0.y), wp, acc[j][0]);
                acc[j][1] = ffma2(make_float2(a0.z, a0.w), wp, acc[j][1]);
                acc[j][2] = ffma2(make_float2(a1.x, a1.y), wp, acc[j][2]);
                acc[j][3] = ffma2(make_float2(a1.z, a1.w), wp, acc[j][3]);
                acc[j][4] = ffma2(make_float2(a2.x, a2.y), wp, acc[j][4]);
                acc[j][5] = ffma2(make_float2(a2.z, a2.w), wp, acc[j][5]);
            }
            if (extra) {
                float2 a3 = *(const float2*)(arow + 12);
#pragma unroll
                for (int j = 0; j < 4; j++)
                    acc[j][6] = ffma2(a3, make_float2(wj[j], wj[j]), acc[j][6]);
            }
        }
        float4 bb = __ldg((const float4*)(b_g1 + c4));
        int pc = extra ? 7 : 6;
        for (int q = 0; q < pc; q++) {
            int m = mb + 2*q;
            float4 lo, hi;
            lo.x = leaky(acc[0][q].x + bb.x); lo.y = leaky(acc[1][q].x + bb.y);
            lo.z = leaky(acc[2][q].x + bb.z); lo.w = leaky(acc[3][q].x + bb.w);
            hi.x = leaky(acc[0][q].y + bb.x); hi.y = leaky(acc[1][q].y + bb.y);
            hi.z = leaky(acc[2][q].y + bb.z); hi.w = leaky(acc[3][q].y + bb.w);
            *(float4*)(g_h1 + (size_t)(n0 + m    )*128 + c4) = lo;
            *(float4*)(g_h1 + (size_t)(n0 + m + 1)*128 + c4) = hi;
        }
    }
}

// ---------------- layer-2 edge aggregation (prefetch pipeline) ----------------
#define CAPA 320
__global__ __launch_bounds__(256) void k_agg128() {
    __shared__ __align__(8) float2 en_s[CAPA];
    __shared__ int   off_s[51];
    __shared__ float dnode[50];
    int n0 = blockIdx.x * 50;
    int g = n0 / N_;
    int lnbase = n0 - g * N_;
    int t = threadIdx.x;

    const float* dv = g_dinv + g*N_;
    if (t < 51) off_s[t] = g_off[g*(N_+1) + lnbase + t];
    if (t < 50) dnode[t] = dv[lnbase + t];
    __syncthreads();
    int e0 = off_s[0];
    int ecnt = off_s[50] - e0;
    const int* rowsg = g_rows + g*E_ + e0;
    for (int i = t; i < ecnt && i < CAPA; i += 256) {
        int r = rowsg[i];
        en_s[i] = make_float2(__int_as_float(r), dv[r]);
    }
    __syncthreads();

    int c = t & 127;
    int msub = t >> 7;
    int mfirst = msub * 25;
    int O0 = off_s[mfirst] - e0;
    int O1 = off_s[mfirst + 25] - e0;
    const float* h1g = g_h1 + (size_t)g * N_ * 128;
    float* outp = g_h1a + (size_t)n0 * 128 + c;

    int m = mfirst;
    int nb = off_s[m + 1] - e0;
    float acc = 0.f;

    float va[4], wa[4];
#pragma unroll
    for (int i = 0; i < 4; i++) {
        int e = O0 + i;
        if (e < O1) {
            float2 en = (e < CAPA) ? en_s[e]
                      : make_float2(__int_as_float(rowsg[e]), dv[rowsg[e]]);
            wa[i] = en.y;
            va[i] = h1g[(size_t)__float_as_int(en.x) * 128 + c];
        }
    }
#pragma unroll 1
    for (int eb = O0; eb < O1; eb += 4) {
        float vb[4], wb[4];
#pragma unroll
        for (int i = 0; i < 4; i++) {
            int e = eb + 4 + i;
            if (e < O1) {
                float2 en = (e < CAPA) ? en_s[e]
                          : make_float2(__int_as_float(rowsg[e]), dv[rowsg[e]]);
                wb[i] = en.y;
                vb[i] = h1g[(size_t)__float_as_int(en.x) * 128 + c];
            }
        }
#pragma unroll
        for (int i = 0; i < 4; i++) {
            int e = eb + i;
            if (e < O1) {
                while (e == nb) {
                    outp[(size_t)m * 128] = acc * dnode[m];
                    acc = 0.f;
                    m++;
                    nb = off_s[m + 1] - e0;
                }
                acc = fmaf(wa[i], va[i], acc);
            }
        }
#pragma unroll
        for (int i = 0; i < 4; i++) { va[i] = vb[i]; wa[i] = wb[i]; }
    }
    for (; m < mfirst + 25; m++) {
        outp[(size_t)m * 128] = acc * dnode[m];
        acc = 0.f;
    }
}

// ---------------- HMMA layer-2 GEMM(64x256x128, bf16x2-split) + max-pool ----------------
// 64 nodes/tile, 256 threads (2M x 4N warps), ~173 KB dynamic smem.
#define SM_POOL 0        // 512 ints
#define SM_BIAS 2048     // 256 floats
#define SM_AHI  3072     // 64*68 words = 17408 B
#define SM_ALO  20480
#define SM_BHI  37888    // 256*68 words = 69632 B
#define SM_BLO  107520
#define SMEM_MM 177152

__global__ __launch_bounds__(256) void k_mma_gemm2pool(const float* __restrict__ b_g2) {
    extern __shared__ __align__(16) char smem[];
    int n0 = blockIdx.x * 64;
    int t = threadIdx.x;
    int lane = t & 31, wid = t >> 5;
    int gq = lane >> 2, tq = lane & 3;
    int warpM = wid & 1, warpN = wid >> 1;

    int* s_pool = (int*)(smem + SM_POOL);
    float* bias = (float*)(smem + SM_BIAS);
    s_pool[t] = 0x80000000;
    s_pool[t + 256] = 0x80000000;
    bias[t] = b_g2[t];

    // stage A: a = h1a + d^2*h1, bf16 hi/lo, [m][k] row stride 68 words
    uint32_t* Ah = (uint32_t*)(smem + SM_AHI);
    uint32_t* Al = (uint32_t*)(smem + SM_ALO);
#pragma unroll 1
    for (int idx = t; idx < 4096; idx += 256) {
        int m = idx >> 6, kp = idx & 63;
        int node = n0 + m;
        float2 a = make_float2(0.f, 0.f);
        if (node < TOT_NODES) {
            float d = g_dinv[node];
            float2 s = *(const float2*)(g_h1 + (size_t)node*128 + kp*2);
            float2 e = *(const float2*)(g_h1a + (size_t)node*128 + kp*2);
            a.x = fmaf(d*d, s.x, e.x);
            a.y = fmaf(d*d, s.y, e.y);
        }
        __nv_bfloat16 h0 = __float2bfloat16(a.x);
        __nv_bfloat16 h1 = __float2bfloat16(a.y);
        __nv_bfloat16 l0 = __float2bfloat16(a.x - __bfloat162float(h0));
        __nv_bfloat16 l1 = __float2bfloat16(a.y - __bfloat162float(h1));
        Ah[m*68 + kp] = (uint32_t)__bfloat16_as_ushort(h0) | ((uint32_t)__bfloat16_as_ushort(h1) << 16);
        Al[m*68 + kp] = (uint32_t)__bfloat16_as_ushort(l0) | ((uint32_t)__bfloat16_as_ushort(l1) << 16);
    }
    // copy W images (L2-hot)
    {
        const float4* sh = (const float4*)g_wimg_hi;
        const float4* sl = (const float4*)g_wimg_lo;
        float4* dh = (float4*)(smem + SM_BHI);
        float4* dl = (float4*)(smem + SM_BLO);
#pragma unroll 1
        for (int i = t; i < 4352; i += 256) {
            dh[i] = sh[i];
            dl[i] = sl[i];
        }
    }
    __syncthreads();

    // MMA mainloop: per warp 2 m-tiles x 8 n-tiles x 8 k-steps x 3 terms
    const uint32_t* Bh = (const uint32_t*)(smem + SM_BHI);
    const uint32_t* Bl = (const uint32_t*)(smem + SM_BLO);
    float acc[2][8][4];
#pragma unroll
    for (int mt = 0; mt < 2; mt++)
#pragma unroll
        for (int nt = 0; nt < 8; nt++)
#pragma unroll
            for (int q = 0; q < 4; q++) acc[mt][nt][q] = 0.f;

#pragma unroll 1
    for (int ks = 0; ks < 8; ks++) {
        int kw = ks*8 + tq;
        uint32_t fah[2][4], fal[2][4];
#pragma unroll
        for (int mt = 0; mt < 2; mt++) {
            int r = warpM*32 + mt*16 + gq;
            fah[mt][0] = Ah[r*68 + kw];
            fah[mt][1] = Ah[(r+8)*68 + kw];
            fah[mt][2] = Ah[r*68 + kw + 4];
            fah[mt][3] = Ah[(r+8)*68 + kw + 4];
            fal[mt][0] = Al[r*68 + kw];
            fal[mt][1] = Al[(r+8)*68 + kw];
            fal[mt][2] = Al[r*68 + kw + 4];
            fal[mt][3] = Al[(r+8)*68 + kw + 4];
        }
#pragma unroll
        for (int nt = 0; nt < 8; nt++) {
            int n = warpN*64 + nt*8 + gq;
            uint32_t bh0 = Bh[n*68 + kw], bh1 = Bh[n*68 + kw + 4];
            uint32_t bl0 = Bl[n*68 + kw], bl1 = Bl[n*68 + kw + 4];
#pragma unroll
            for (int mt = 0; mt < 2; mt++) {
                mma_bf16(acc[mt][nt], fah[mt], bh0, bh1);
                mma_bf16(acc[mt][nt], fah[mt], bl0, bl1);
                mma_bf16(acc[mt][nt], fal[mt], bh0, bh1);
            }
        }
    }

    // epilogue: bias + leaky, per-graph masked max, smem pool
    int gA = n0 / N_;
    int gAend = (gA + 1) * N_;
    int lastn = n0 + 63;
    if (lastn >= TOT_NODES) lastn = TOT_NODES - 1;
    int gB = lastn / N_;
    bool straddle = (gB != gA);

#pragma unroll
    for (int nt = 0; nt < 8; nt++) {
        int col0 = warpN*64 + nt*8 + 2*tq;
        float b0 = bias[col0], b1 = bias[col0 + 1];
        float mA0 = -1e30f, mA1 = -1e30f, mB0 = -1e30f, mB1 = -1e30f;
#pragma unroll
        for (int mt = 0; mt < 2; mt++) {
#pragma unroll
            for (int hh = 0; hh < 2; hh++) {
                int r = warpM*32 + mt*16 + gq + 8*hh;
                int node = n0 + r;
                if (node < TOT_NODES) {
                    float v0 = leaky(acc[mt][nt][2*hh]     + b0);
                    float v1 = leaky(acc[mt][nt][2*hh + 1] + b1);
                    if (node < gAend) { mA0 = fmaxf(mA0, v0); mA1 = fmaxf(mA1, v1); }
                    else              { mB0 = fmaxf(mB0, v0); mB1 = fmaxf(mB1, v1); }
                }
            }
        }
#pragma unroll
        for (int o = 4; o < 32; o <<= 1) {
            mA0 = fmaxf(mA0, __shfl_xor_sync(0xffffffffu, mA0, o));
            mA1 = fmaxf(mA1, __shfl_xor_sync(0xffffffffu, mA1, o));
            if (straddle) {
                mB0 = fmaxf(mB0, __shfl_xor_sync(0xffffffffu, mB0, o));
                mB1 = fmaxf(mB1, __shfl_xor_sync(0xffffffffu, mB1, o));
            }
        }
        if (gq == 0) {
            atomicMax(&s_pool[col0],     fkey(mA0));
            atomicMax(&s_pool[col0 + 1], fkey(mA1));
            if (straddle) {
                atomicMax(&s_pool[256 + col0],     fkey(mB0));
                atomicMax(&s_pool[256 + col0 + 1], fkey(mB1));
            }
        }
    }
    __syncthreads();
    int pv = s_pool[t];
    if (pv != (int)0x80000000) atomicMax(&g_pool[gA*256 + t], pv);
    if (straddle) {
        int pb = s_pool[256 + t];
        if (pb != (int)0x80000000) atomicMax(&g_pool[gB*256 + t], pb);
    }
}

// decode pool, FC(256->32, relu) + pe; seeds mu/sigma rows. grid G_, 256 thr.
__global__ void k_fc(const float* __restrict__ W_fc, const float* __restrict__ b_fc,
                     const float* __restrict__ pe, const float* __restrict__ muQ,
                     const float* __restrict__ sigQ) {
    int g = blockIdx.x;
    int t = threadIdx.x;
    __shared__ float ps[256];
    ps[t] = fdec(g_pool[g*256 + t]);
    __syncthreads();
    if (t < 32) {
        float acc = b_fc[t];
        for (int k = 0; k < 256; k++) acc = fmaf(ps[k], W_fc[k*32 + t], acc);
        acc = fmaxf(acc, 0.0f);
        int b = g / 50, s = g - b*50;
        int tk = 2 + s;
        g_xseq[(tk*2 + b)*D_ + t] = acc + pe[tk*D_ + t];
    }
    if (g == 0 && t >= 128 && t < 256) {
        int i = t - 128;
        if (i < 128) {
            int tk = i >> 6;
            int bb = (i >> 5) & 1;
            int d = i & 31;
            g_xseq[(tk*2 + bb)*D_ + d] = (tk == 0 ? muQ[d] : sigQ[d]) + pe[tk*D_ + d];
        }
    }
}

// ---------------- single-kernel transformer ----------------
__device__ __forceinline__ void grid_bar(int target) {
    __syncthreads();
    if (threadIdx.x == 0) {
        __threadfence();
        int v = atomicAdd(&g_bar_cnt, 1);
        if (v + 1 == NB_ * target) {
            g_bar_gen = target;
        } else {
            while (g_bar_gen < target) { }
        }
        __threadfence();
    }
    __syncthreads();
}

__global__ __launch_bounds__(256) void k_transformer(
        const float* __restrict__ in_w, const float* __restrict__ in_b,
        const float* __restrict__ out_w, const float* __restrict__ out_b,
        const float* __restrict__ ln1g, const float* __restrict__ ln1b,
        const float* __restrict__ w1, const float* __restrict__ b1,
        const float* __restrict__ w2, const float* __restrict__ b2,
        const float* __restrict__ ln2g, const float* __restrict__ ln2b,
        float* __restrict__ out) {
    __shared__ float wsq[96*33];
    __shared__ float ow[32*33];
    __shared__ __align__(16) float xv[32];
    __shared__ float at[32];
    __shared__ __align__(16) float xs[32];
    __shared__ float gs[1024];
    __shared__ float ffo[32];
    int tau = blockIdx.x;
    int t = threadIdx.x;
    int wid = t >> 5, lane = t & 31;
    int b = tau & 1;

    if (t < 32) xv[t] = g_xseq[tau*32 + t];

    for (int l = 0; l < 4; l++) {
        for (int idx = t; idx < 96*32; idx += 256)
            wsq[(idx >> 5)*33 + (idx & 31)] = in_w[l*96*32 + idx];
        for (int idx = t; idx < 1024; idx += 256)
            ow[(idx >> 5)*33 + (idx & 31)] = out_w[l*1024 + idx];
        __syncthreads();

        float* qk = g_qkvbuf[l & 1];
        if (t < 96) {
            float acc = in_b[l*96 + t];
#pragma unroll
            for (int d = 0; d < 32; d++) acc = fmaf(xv[d], wsq[t*33 + d], acc);
            qk[tau*96 + t] = acc;
        }
        grid_bar(l + 1);

        if (wid < 4) {
            int h = wid;
            float4 qa = *(const float4*)(qk + tau*96 + h*8);
            float4 qb = *(const float4*)(qk + tau*96 + h*8 + 4);
            int s0 = lane, s1 = lane + 32;
            const float* k0 = qk + (s0*2 + b)*96 + 32 + h*8;
            float4 ka = *(const float4*)(k0);
            float4 kb = *(const float4*)(k0 + 4);
            float sc0 = (qa.x*ka.x + qa.y*ka.y + qa.z*ka.z + qa.w*ka.w +
                         qb.x*kb.x + qb.y*kb.y + qb.z*kb.z + qb.w*kb.w) * 0.35355339059327373f;
            const float* v0p = qk + (s0*2 + b)*96 + 64 + h*8;
            float4 va = *(const float4*)(v0p);
            float4 vb = *(const float4*)(v0p + 4);
            float sc1 = -1e30f;
            float4 wa = make_float4(0.f,0.f,0.f,0.f), wb = wa;
            if (s1 < T_) {
                const float* k1 = qk + (s1*2 + b)*96 + 32 + h*8;
                float4 kc = *(const float4*)(k1);
                float4 kd = *(const float4*)(k1 + 4);
                sc1 = (qa.x*kc.x + qa.y*kc.y + qa.z*kc.z + qa.w*kc.w +
                       qb.x*kd.x + qb.y*kd.y + qb.z*kd.z + qb.w*kd.w) * 0.35355339059327373f;
                const float* v1p = qk + (s1*2 + b)*96 + 64 + h*8;
                wa = *(const float4*)(v1p);
                wb = *(const float4*)(v1p + 4);
            }
            float mx = warp_max(fmaxf(sc0, sc1));
            float p0 = expf(sc0 - mx);
            float p1 = (s1 < T_) ? expf(sc1 - mx) : 0.f;
            float sum = warp_sum(p0 + p1);
            float o[8];
            o[0] = p0*va.x + p1*wa.x;  o[1] = p0*va.y + p1*wa.y;
            o[2] = p0*va.z + p1*wa.z;  o[3] = p0*va.w + p1*wa.w;
            o[4] = p0*vb.x + p1*wb.x;  o[5] = p0*vb.y + p1*wb.y;
            o[6] = p0*vb.z + p1*wb.z;  o[7] = p0*vb.w + p1*wb.w;
#pragma unroll
            for (int e = 0; e < 8; e++) o[e] = warp_sum(o[e]);
            if (lane == 0) {
                float inv = 1.0f / sum;
#pragma unroll
                for (int e = 0; e < 8; e++) at[h*8 + e] = o[e] * inv;
            }
        }
        __syncthreads();

        if (t < 32) {
            float o = out_b[l*32 + t];
#pragma unroll
            for (int c = 0; c < 32; c++) o = fmaf(at[c], ow[t*33 + c], o);
            float val = xv[t] + o;
            float mean = warp_sum(val) * (1.0f/32.0f);
            float dvv = val - mean;
            float var = warp_sum(dvv*dvv) * (1.0f/32.0f);
            xs[t] = dvv * rsqrtf(var + 1e-5f) * ln1g[l*32 + t] + ln1b[l*32 + t];
        }
        __syncthreads();

        float4 xr[8];
#pragma unroll
        for (int i = 0; i < 8; i++) xr[i] = *(const float4*)(xs + i*4);
        const float* w1l = w1 + (size_t)l*1024*32;
        const float* b1l = b1 + l*1024;
#pragma unroll
        for (int i = 0; i < 4; i++) {
            int f = t*4 + i;
            float acc = b1l[f];
            const float4* wr = (const float4*)(w1l + (size_t)f*32);
#pragma unroll
            for (int d4 = 0; d4 < 8; d4++) {
                float4 w = wr[d4];
                float4 x = xr[d4];
                acc = fmaf(w.x, x.x, acc);
                acc = fmaf(w.y, x.y, acc);
                acc = fmaf(w.z, x.z, acc);
                acc = fmaf(w.w, x.w, acc);
            }
            gs[f] = 0.5f * acc * (1.0f + erff(acc * 0.70710678118654752f));
        }
        __syncthreads();
        const float* w2l = w2 + (size_t)l*32*1024;
#pragma unroll
        for (int pass = 0; pass < 4; pass++) {
            int d = pass*8 + wid;
            const float* wrow = w2l + (size_t)d*1024;
            float p = 0.f;
#pragma unroll 8
            for (int j = 0; j < 32; j++) p = fmaf(gs[j*32 + lane], wrow[j*32 + lane], p);
            p = warp_sum(p);
            if (lane == 0) ffo[d] = p;
        }
        __syncthreads();
        if (t < 32) {
            float val = xs[t] + ffo[t] + b2[l*32 + t];
            float mean = warp_sum(val) * (1.0f/32.0f);
            float dvv = val - mean;
            float var = warp_sum(dvv*dvv) * (1.0f/32.0f);
            xv[t] = dvv * rsqrtf(var + 1e-5f) * ln2g[l*32 + t] + ln2b[l*32 + t];
        }
        __syncthreads();
    }

    if (t < 32) {
        float y = xv[t];
        out[128 + tau*32 + t] = y;
        if (tau < 4) out[tau*32 + t] = y;
    }
}

// ---------------- launch ----------------
extern "C" void kernel_launch(void* const* d_in, const int* in_sizes, int n_in,
                              void* d_out, int out_size) {
    const float* v     = (const float*)d_in[0];
    const int*   edge  = (const int*)d_in[2];
    const float* W_emb = (const float*)d_in[3];
    const float* b_emb = (const float*)d_in[4];
    const float* W_g1  = (const float*)d_in[5];
    const float* b_g1  = (const float*)d_in[6];
    const float* W_g2  = (const float*)d_in[7];
    const float* b_g2  = (const float*)d_in[8];
    const float* W_fc  = (const float*)d_in[9];
    const float* b_fc  = (const float*)d_in[10];
    const float* muQ   = (const float*)d_in[11];
    const float* sigQ  = (const float*)d_in[12];
    const float* pe    = (const float*)d_in[13];
    const float* in_w  = (const float*)d_in[14];
    const float* in_b  = (const float*)d_in[15];
    const float* out_w = (const float*)d_in[16];
    const float* out_b = (const float*)d_in[17];
    const float* ln1g  = (const float*)d_in[18];
    const float* ln1b  = (const float*)d_in[19];
    const float* w1    = (const float*)d_in[20];
    const float* b1    = (const float*)d_in[21];
    const float* w2    = (const float*)d_in[22];
    const float* b2    = (const float*)d_in[23];
    const float* ln2g  = (const float*)d_in[24];
    const float* ln2b  = (const float*)d_in[25];

    static int smem_set = 0;
    if (!smem_set) {
        cudaFuncSetAttribute(k_mma_gemm2pool,
                             cudaFuncAttributeMaxDynamicSharedMemorySize, SMEM_MM);
        smem_set = 1;
    }

    k_prep<<<G_, 256>>>(edge, W_g2);                             // 0
    k_agg_gemm1<<<5000, 128>>>(v, W_emb, b_emb, W_g1, b_g1);     // 1
    k_agg128<<<5000, 256>>>();                                   // 2
    k_mma_gemm2pool<<<NT_, 256, SMEM_MM>>>(b_g2);                // 3 <- ncu capture slot
    k_fc<<<G_, 256>>>(W_fc, b_fc, pe, muQ, sigQ);                // 4
    k_transformer<<<NB_, 256>>>(in_w, in_b, out_w, out_b, ln1g, ln1b,
                                w1, b1, w2, b2, ln2g, ln2b, (float*)d_out);  // 5
}

// round 12
// speedup vs baseline: 1.3456x; 1.3456x over previous
#include <cuda_runtime.h>
#include <cuda_bf16.h>
#include <math.h>
#include <stdint.h>

// ---------------- problem constants ----------------
#define G_  100        // B*S graphs
#define N_  2500       // nodes per graph
#define E_  7500       // edges per graph
#define TOT_NODES 250000
#define TOT_EDGES 750000
#define T_  52         // sequence length (S+2)
#define D_  32         // d_model
#define NB_ 104        // transformer blocks (tokens)
#define NT_ 3907       // ceil(250000/64) mma tiles

// ---------------- scratch (static, allocation-free) ----------------
__device__ float g_h1[TOT_NODES * 128];       // 128 MB
__device__ float g_h1a[TOT_NODES * 128];      // 128 MB (edge-aggregated h1)
__device__ float g_dinv[TOT_NODES];
__device__ int   g_off[G_*(N_+1)];
__device__ int   g_rows[TOT_EDGES];
__device__ int   g_pool[G_*256];
__device__ float g_xseq[T_*2*D_];             // [t][b][d]
__device__ float g_qkvbuf[2][NB_*96];
__device__ int   g_bar_cnt;
__device__ volatile int g_bar_gen;
// bf16 hi/lo images of W_g2^T as [n][k], row stride 136 bf16 (68 words)
__device__ __align__(16) unsigned char g_wimg_hi[69632];
__device__ __align__(16) unsigned char g_wimg_lo[69632];

// ---------------- helpers ----------------
__device__ __forceinline__ float2 ffma2(float2 a, float2 b, float2 c) {
    union U { float2 f; unsigned long long u; } ua, ub, uc;
    ua.f = a; ub.f = b; uc.f = c;
    asm("fma.rn.f32x2 %0, %1, %2, %3;" : "=l"(uc.u) : "l"(ua.u), "l"(ub.u), "l"(uc.u));
    return uc.f;
}

__device__ __forceinline__ float warp_sum(float v) {
#pragma unroll
    for (int o = 16; o; o >>= 1) v += __shfl_xor_sync(0xffffffffu, v, o);
    return v;
}
__device__ __forceinline__ float warp_max(float v) {
#pragma unroll
    for (int o = 16; o; o >>= 1) v = fmaxf(v, __shfl_xor_sync(0xffffffffu, v, o));
    return v;
}

__device__ __forceinline__ float leaky(float x) {
    return x >= 0.0f ? x : 0.15f * x;
}

__device__ __forceinline__ int fkey(float f) {
    int i = __float_as_int(f);
    return i >= 0 ? i : (i ^ 0x7FFFFFFF);
}
__device__ __forceinline__ float fdec(int k) {
    return __int_as_float(k >= 0 ? k : (k ^ 0x7FFFFFFF));
}

// mma.sync m16n8k16 bf16 * bf16 -> f32 (baseline PTX; valid on sm_100 target)
__device__ __forceinline__ void mma_bf16(float* c, const uint32_t* a,
                                         uint32_t b0, uint32_t b1) {
    asm volatile(
        "mma.sync.aligned.m16n8k16.row.col.f32.bf16.bf16.f32 "
        "{%0,%1,%2,%3}, {%4,%5,%6,%7}, {%8,%9}, {%0,%1,%2,%3};"
        : "+f"(c[0]), "+f"(c[1]), "+f"(c[2]), "+f"(c[3])
        : "r"(a[0]), "r"(a[1]), "r"(a[2]), "r"(a[3]), "r"(b0), "r"(b1));
}

// ---------------- fused graph prep (+ W_g2 bf16 image build) ----------------
__global__ __launch_bounds__(256) void k_prep(const int* __restrict__ edge,
                                              const float* __restrict__ W_g2) {
    __shared__ int cnt[N_];
    __shared__ int cur[N_];
    __shared__ int sm[256];
    int g = blockIdx.x;
    int t = threadIdx.x;
    for (int i = t; i < N_; i += 256) cnt[i] = 0;
    __syncthreads();

    const int2* eg = (const int2*)edge + (size_t)g * E_;
    for (int i = t; i < E_; i += 256) {
        int2 rc = eg[i];
        atomicAdd(&cnt[rc.y], 1);
    }
    __syncthreads();

    int base = t * 10;
    int loc[10];
    int s = 0;
    if (base < N_) {
#pragma unroll
        for (int i = 0; i < 10; i++) { loc[i] = cnt[base + i]; s += loc[i]; }
    }
    sm[t] = s;
    __syncthreads();
    for (int o = 1; o < 256; o <<= 1) {
        int vv = (t >= o) ? sm[t - o] : 0;
        __syncthreads();
        sm[t] += vv;
        __syncthreads();
    }
    int excl = sm[t] - s;
    if (base < N_) {
        int off = excl;
#pragma unroll
        for (int i = 0; i < 10; i++) {
            g_off[g*(N_+1) + base + i] = off;
            cur[base + i] = off;
            g_dinv[g*N_ + base + i] = rsqrtf((float)loc[i] + 1.0f);
            off += loc[i];
        }
    }
    if (t == 255) g_off[g*(N_+1) + N_] = sm[255];
    __syncthreads();

    for (int i = t; i < E_; i += 256) {
        int2 rc = eg[i];
        int pos = atomicAdd(&cur[rc.y], 1);
        g_rows[(size_t)g*E_ + pos] = rc.x;
    }

    g_pool[g*256 + t] = 0x80000000;
    if (g == 0 && t == 0) { g_bar_cnt = 0; g_bar_gen = 0; }

    // W image: B[n][k] = W_g2[k][n] as bf16 hi/lo, row stride 136 bf16
    for (int idx = g*256 + t; idx < 32768; idx += G_*256) {
        int k = idx >> 8, n = idx & 255;
        float w = W_g2[k*256 + n];
        __nv_bfloat16 hi = __float2bfloat16(w);
        __nv_bfloat16 lo = __float2bfloat16(w - __bfloat162float(hi));
        ((unsigned short*)g_wimg_hi)[n*136 + k] = __bfloat16_as_ushort(hi);
        ((unsigned short*)g_wimg_lo)[n*136 + k] = __bfloat16_as_ushort(lo);
    }
}

// ---------------- fused GCN layer 1: embed + aggregate + GEMM(64->128) ----------------
#define CAP1 320
__global__ __launch_bounds__(128) void k_agg_gemm1(
        const float* __restrict__ v, const float* __restrict__ W_emb,
        const float* __restrict__ b_emb, const float* __restrict__ W_g1,
        const float* __restrict__ b_g1) {
    __shared__ __align__(16) float As[64*56];
    __shared__ __align__(16) float4 ed_s[CAP1];
    __shared__ int   off_s[51];
    __shared__ float dnode[50];
    __shared__ float vself[50*3];
    int n0 = blockIdx.x * 50;
    int g = n0 / N_;
    int lnbase = n0 - g * N_;
    int t  = threadIdx.x;

    const float* dv = g_dinv + g*N_;
    const float* vg = v + (size_t)g * N_ * 3;
    if (t < 51) off_s[t] = g_off[g*(N_+1) + lnbase + t];
    if (t < 50) dnode[t] = dv[lnbase + t];
    for (int idx = t; idx < 150; idx += 128) vself[idx] = vg[(size_t)lnbase*3 + idx];
    __syncthreads();
    int e0 = off_s[0];
    int ecnt = off_s[50] - e0;
    const int* rowsg = g_rows + g*E_ + e0;
    for (int i = t; i < ecnt && i < CAP1; i += 128) {
        int r = rowsg[i];
        const float* vp = vg + (size_t)r*3;
        ed_s[i] = make_float4(vp[0], vp[1], vp[2], dv[r]);
    }
    __syncthreads();

    {
        int c = t & 63;
        int msub = t >> 6;
        float we0 = __ldg(W_emb + c), we1 = __ldg(W_emb + 64 + c);
        float we2 = __ldg(W_emb + 128 + c), be = __ldg(b_emb + c);
#pragma unroll 1
        for (int p = 0; p < 25; p++) {
            int m = p*2 + msub;
            float di = dnode[m];
            float xv = fmaxf(fmaf(vself[m*3+2], we2,
                         fmaf(vself[m*3+1], we1, fmaf(vself[m*3], we0, be))), 0.f);
            float acc = di * di * xv;
            int o0 = off_s[m] - e0, o1 = off_s[m+1] - e0;
            for (int e = o0; e < o1; e++) {
                float4 ed;
                if (e < CAP1) ed = ed_s[e];
                else {
                    int r = rowsg[e];
                    const float* vq = vg + (size_t)r*3;
                    ed = make_float4(vq[0], vq[1], vq[2], dv[r]);
                }
                float xn = fmaxf(fmaf(ed.z, we2, fmaf(ed.y, we1, fmaf(ed.x, we0, be))), 0.f);
                acc = fmaf(di * ed.w, xn, acc);
            }
            As[c*56 + m] = acc;
        }
    }
    __syncthreads();

    {
        int c4 = (t & 31) * 4;
        int mh = t >> 5;
        int mb = mh * 12;
        bool extra = (mh == 3);
        float2 acc[4][7];
#pragma unroll
        for (int j = 0; j < 4; j++)
#pragma unroll
            for (int q = 0; q < 7; q++) acc[j][q] = make_float2(0.f, 0.f);

        const float* Wp = W_g1 + c4;
#pragma unroll 2
        for (int k = 0; k < 64; k++) {
            float4 wv = __ldg((const float4*)(Wp + k*128));
            const float* arow = As + k*56 + mb;
            float4 a0 = *(const float4*)(arow);
            float4 a1 = *(const float4*)(arow + 4);
            float4 a2 = *(const float4*)(arow + 8);
            float wj[4] = {wv.x, wv.y, wv.z, wv.w};
#pragma unroll
            for (int j = 0; j < 4; j++) {
                float2 wp = make_float2(wj[j], wj[j]);
                acc[j][0] = ffma2(make_float2(a0.x, a0.y), wp, acc[j][0]);
                acc[j][1] = ffma2(make_float2(a0.z, a0.w), wp, acc[j][1]);
                acc[j][2] = ffma2(make_float2(a1.x, a1.y), wp, acc[j][2]);
                acc[j][3] = ffma2(make_float2(a1.z, a1.w), wp, acc[j][3]);
                acc[j][4] = ffma2(make_float2(a2.x, a2.y), wp, acc[j][4]);
                acc[j][5] = ffma2(make_float2(a2.z, a2.w), wp, acc[j][5]);
            }
            if (extra) {
                float2 a3 = *(const float2*)(arow + 12);
#pragma unroll
                for (int j = 0; j < 4; j++)
                    acc[j][6] = ffma2(a3, make_float2(wj[j], wj[j]), acc[j][6]);
            }
        }
        float4 bb = __ldg((const float4*)(b_g1 + c4));
        int pc = extra ? 7 : 6;
        for (int q = 0; q < pc; q++) {
            int m = mb + 2*q;
            float4 lo, hi;
            lo.x = leaky(acc[0][q].x + bb.x); lo.y = leaky(acc[1][q].x + bb.y);
            lo.z = leaky(acc[2][q].x + bb.z); lo.w = leaky(acc[3][q].x + bb.w);
            hi.x = leaky(acc[0][q].y + bb.x); hi.y = leaky(acc[1][q].y + bb.y);
            hi.z = leaky(acc[2][q].y + bb.z); hi.w = leaky(acc[3][q].y + bb.w);
            *(float4*)(g_h1 + (size_t)(n0 + m    )*128 + c4) = lo;
            *(float4*)(g_h1 + (size_t)(n0 + m + 1)*128 + c4) = hi;
        }
    }
}

// ---------------- layer-2 edge aggregation (prefetch pipeline) ----------------
#define CAPA 320
__global__ __launch_bounds__(256) void k_agg128() {
    __shared__ __align__(8) float2 en_s[CAPA];
    __shared__ int   off_s[51];
    __shared__ float dnode[50];
    int n0 = blockIdx.x * 50;
    int g = n0 / N_;
    int lnbase = n0 - g * N_;
    int t = threadIdx.x;

    const float* dv = g_dinv + g*N_;
    if (t < 51) off_s[t] = g_off[g*(N_+1) + lnbase + t];
    if (t < 50) dnode[t] = dv[lnbase + t];
    __syncthreads();
    int e0 = off_s[0];
    int ecnt = off_s[50] - e0;
    const int* rowsg = g_rows + g*E_ + e0;
    for (int i = t; i < ecnt && i < CAPA; i += 256) {
        int r = rowsg[i];
        en_s[i] = make_float2(__int_as_float(r), dv[r]);
    }
    __syncthreads();

    int c = t & 127;
    int msub = t >> 7;
    int mfirst = msub * 25;
    int O0 = off_s[mfirst] - e0;
    int O1 = off_s[mfirst + 25] - e0;
    const float* h1g = g_h1 + (size_t)g * N_ * 128;
    float* outp = g_h1a + (size_t)n0 * 128 + c;

    int m = mfirst;
    int nb = off_s[m + 1] - e0;
    float acc = 0.f;

    float va[4], wa[4];
#pragma unroll
    for (int i = 0; i < 4; i++) {
        int e = O0 + i;
        if (e < O1) {
            float2 en = (e < CAPA) ? en_s[e]
                      : make_float2(__int_as_float(rowsg[e]), dv[rowsg[e]]);
            wa[i] = en.y;
            va[i] = h1g[(size_t)__float_as_int(en.x) * 128 + c];
        }
    }
#pragma unroll 1
    for (int eb = O0; eb < O1; eb += 4) {
        float vb[4], wb[4];
#pragma unroll
        for (int i = 0; i < 4; i++) {
            int e = eb + 4 + i;
            if (e < O1) {
                float2 en = (e < CAPA) ? en_s[e]
                          : make_float2(__int_as_float(rowsg[e]), dv[rowsg[e]]);
                wb[i] = en.y;
                vb[i] = h1g[(size_t)__float_as_int(en.x) * 128 + c];
            }
        }
#pragma unroll
        for (int i = 0; i < 4; i++) {
            int e = eb + i;
            if (e < O1) {
                while (e == nb) {
                    outp[(size_t)m * 128] = acc * dnode[m];
                    acc = 0.f;
                    m++;
                    nb = off_s[m + 1] - e0;
                }
                acc = fmaf(wa[i], va[i], acc);
            }
        }
#pragma unroll
        for (int i = 0; i < 4; i++) { va[i] = vb[i]; wa[i] = wb[i]; }
    }
    for (; m < mfirst + 25; m++) {
        outp[(size_t)m * 128] = acc * dnode[m];
        acc = 0.f;
    }
}

// ---------------- HMMA layer-2 GEMM(64x256x128, bf16x2-split) + max-pool ----------------
// 64 nodes/tile, 256 threads (2M x 4N warps). B fragments straight from L2
// (g_wimg is shared by all blocks); smem = A hi/lo only (~38 KB) -> 2 blocks/SM.
__global__ __launch_bounds__(256, 2) void k_mma_gemm2pool(const float* __restrict__ b_g2) {
    __shared__ int s_pool[512];
    __shared__ float bias_s[256];
    __shared__ __align__(16) uint32_t Ah[64*68];   // 17408 B
    __shared__ __align__(16) uint32_t Al[64*68];   // 17408 B
    int n0 = blockIdx.x * 64;
    int t = threadIdx.x;
    int lane = t & 31, wid = t >> 5;
    int gq = lane >> 2, tq = lane & 3;
    int warpM = wid & 1, warpN = wid >> 1;

    s_pool[t] = 0x80000000;
    s_pool[t + 256] = 0x80000000;
    bias_s[t] = b_g2[t];

    // stage A: a = h1a + d^2*h1, bf16 hi/lo, [m][k] row stride 68 words
#pragma unroll 1
    for (int idx = t; idx < 4096; idx += 256) {
        int m = idx >> 6, kp = idx & 63;
        int node = n0 + m;
        float2 a = make_float2(0.f, 0.f);
        if (node < TOT_NODES) {
            float d = g_dinv[node];
            float2 s = *(const float2*)(g_h1 + (size_t)node*128 + kp*2);
            float2 e = *(const float2*)(g_h1a + (size_t)node*128 + kp*2);
            a.x = fmaf(d*d, s.x, e.x);
            a.y = fmaf(d*d, s.y, e.y);
        }
        __nv_bfloat16 h0 = __float2bfloat16(a.x);
        __nv_bfloat16 h1 = __float2bfloat16(a.y);
        __nv_bfloat16 l0 = __float2bfloat16(a.x - __bfloat162float(h0));
        __nv_bfloat16 l1 = __float2bfloat16(a.y - __bfloat162float(h1));
        Ah[m*68 + kp] = (uint32_t)__bfloat16_as_ushort(h0) | ((uint32_t)__bfloat16_as_ushort(h1) << 16);
        Al[m*68 + kp] = (uint32_t)__bfloat16_as_ushort(l0) | ((uint32_t)__bfloat16_as_ushort(l1) << 16);
    }
    __syncthreads();

    // MMA mainloop: per warp 2 m-tiles x 8 n-tiles x 8 k-steps x 3 terms.
    // B fragments loaded from global (L2-resident, identical across blocks).
    const uint32_t* BhG = (const uint32_t*)g_wimg_hi;
    const uint32_t* BlG = (const uint32_t*)g_wimg_lo;
    float acc[2][8][4];
#pragma unroll
    for (int mt = 0; mt < 2; mt++)
#pragma unroll
        for (int nt = 0; nt < 8; nt++)
#pragma unroll
            for (int q = 0; q < 4; q++) acc[mt][nt][q] = 0.f;

#pragma unroll 1
    for (int ks = 0; ks < 8; ks++) {
        int kw = ks*8 + tq;
        uint32_t fah[2][4], fal[2][4];
#pragma unroll
        for (int mt = 0; mt < 2; mt++) {
            int r = warpM*32 + mt*16 + gq;
            fah[mt][0] = Ah[r*68 + kw];
            fah[mt][1] = Ah[(r+8)*68 + kw];
            fah[mt][2] = Ah[r*68 + kw + 4];
            fah[mt][3] = Ah[(r+8)*68 + kw + 4];
            fal[mt][0] = Al[r*68 + kw];
            fal[mt][1] = Al[(r+8)*68 + kw];
            fal[mt][2] = Al[r*68 + kw + 4];
            fal[mt][3] = Al[(r+8)*68 + kw + 4];
        }
#pragma unroll
        for (int half = 0; half < 2; half++) {
            uint32_t bh[4][2], bl[4][2];
#pragma unroll
            for (int j = 0; j < 4; j++) {
                int n = warpN*64 + (half*4 + j)*8 + gq;
                bh[j][0] = __ldg(BhG + n*68 + kw);
                bh[j][1] = __ldg(BhG + n*68 + kw + 4);
                bl[j][0] = __ldg(BlG + n*68 + kw);
                bl[j][1] = __ldg(BlG + n*68 + kw + 4);
            }
#pragma unroll
            for (int j = 0; j < 4; j++) {
                int nt = half*4 + j;
#pragma unroll
                for (int mt = 0; mt < 2; mt++) {
                    mma_bf16(acc[mt][nt], fah[mt], bh[j][0], bh[j][1]);
                    mma_bf16(acc[mt][nt], fah[mt], bl[j][0], bl[j][1]);
                    mma_bf16(acc[mt][nt], fal[mt], bh[j][0], bh[j][1]);
                }
            }
        }
    }

    // epilogue: bias + leaky, per-graph masked max, smem pool
    int gA = n0 / N_;
    int gAend = (gA + 1) * N_;
    int lastn = n0 + 63;
    if (lastn >= TOT_NODES) lastn = TOT_NODES - 1;
    int gB = lastn / N_;
    bool straddle = (gB != gA);

#pragma unroll
    for (int nt = 0; nt < 8; nt++) {
        int col0 = warpN*64 + nt*8 + 2*tq;
        float b0 = bias_s[col0], b1 = bias_s[col0 + 1];
        float mA0 = -1e30f, mA1 = -1e30f, mB0 = -1e30f, mB1 = -1e30f;
#pragma unroll
        for (int mt = 0; mt < 2; mt++) {
#pragma unroll
            for (int hh = 0; hh < 2; hh++) {
                int r = warpM*32 + mt*16 + gq + 8*hh;
                int node = n0 + r;
                if (node < TOT_NODES) {
                    float v0 = leaky(acc[mt][nt][2*hh]     + b0);
                    float v1 = leaky(acc[mt][nt][2*hh + 1] + b1);
                    if (node < gAend) { mA0 = fmaxf(mA0, v0); mA1 = fmaxf(mA1, v1); }
                    else              { mB0 = fmaxf(mB0, v0); mB1 = fmaxf(mB1, v1); }
                }
            }
        }
#pragma unroll
        for (int o = 4; o < 32; o <<= 1) {
            mA0 = fmaxf(mA0, __shfl_xor_sync(0xffffffffu, mA0, o));
            mA1 = fmaxf(mA1, __shfl_xor_sync(0xffffffffu, mA1, o));
            if (straddle) {
                mB0 = fmaxf(mB0, __shfl_xor_sync(0xffffffffu, mB0, o));
                mB1 = fmaxf(mB1, __shfl_xor_sync(0xffffffffu, mB1, o));
            }
        }
        if (gq == 0) {
            atomicMax(&s_pool[col0],     fkey(mA0));
            atomicMax(&s_pool[col0 + 1], fkey(mA1));
            if (straddle) {
                atomicMax(&s_pool[256 + col0],     fkey(mB0));
                atomicMax(&s_pool[256 + col0 + 1], fkey(mB1));
            }
        }
    }
    __syncthreads();
    int pv = s_pool[t];
    if (pv != (int)0x80000000) atomicMax(&g_pool[gA*256 + t], pv);
    if (straddle) {
        int pb = s_pool[256 + t];
        if (pb != (int)0x80000000) atomicMax(&g_pool[gB*256 + t], pb);
    }
}

// decode pool, FC(256->32, relu) + pe; seeds mu/sigma rows. grid G_, 256 thr.
__global__ void k_fc(const float* __restrict__ W_fc, const float* __restrict__ b_fc,
                     const float* __restrict__ pe, const float* __restrict__ muQ,
                     const float* __restrict__ sigQ) {
    int g = blockIdx.x;
    int t = threadIdx.x;
    __shared__ float ps[256];
    ps[t] = fdec(g_pool[g*256 + t]);
    __syncthreads();
    if (t < 32) {
        float acc = b_fc[t];
        for (int k = 0; k < 256; k++) acc = fmaf(ps[k], W_fc[k*32 + t], acc);
        acc = fmaxf(acc, 0.0f);
        int b = g / 50, s = g - b*50;
        int tk = 2 + s;
        g_xseq[(tk*2 + b)*D_ + t] = acc + pe[tk*D_ + t];
    }
    if (g == 0 && t >= 128 && t < 256) {
        int i = t - 128;
        if (i < 128) {
            int tk = i >> 6;
            int bb = (i >> 5) & 1;
            int d = i & 31;
            g_xseq[(tk*2 + bb)*D_ + d] = (tk == 0 ? muQ[d] : sigQ[d]) + pe[tk*D_ + d];
        }
    }
}

// ---------------- single-kernel transformer ----------------
__device__ __forceinline__ void grid_bar(int target) {
    __syncthreads();
    if (threadIdx.x == 0) {
        __threadfence();
        int v = atomicAdd(&g_bar_cnt, 1);
        if (v + 1 == NB_ * target) {
            g_bar_gen = target;
        } else {
            while (g_bar_gen < target) { }
        }
        __threadfence();
    }
    __syncthreads();
}

__global__ __launch_bounds__(256) void k_transformer(
        const float* __restrict__ in_w, const float* __restrict__ in_b,
        const float* __restrict__ out_w, const float* __restrict__ out_b,
        const float* __restrict__ ln1g, const float* __restrict__ ln1b,
        const float* __restrict__ w1, const float* __restrict__ b1,
        const float* __restrict__ w2, const float* __restrict__ b2,
        const float* __restrict__ ln2g, const float* __restrict__ ln2b,
        float* __restrict__ out) {
    __shared__ float wsq[96*33];
    __shared__ float ow[32*33];
    __shared__ __align__(16) float xv[32];
    __shared__ float at[32];
    __shared__ __align__(16) float xs[32];
    __shared__ float gs[1024];
    __shared__ float ffo[32];
    int tau = blockIdx.x;
    int t = threadIdx.x;
    int wid = t >> 5, lane = t & 31;
    int b = tau & 1;

    if (t < 32) xv[t] = g_xseq[tau*32 + t];

    for (int l = 0; l < 4; l++) {
        for (int idx = t; idx < 96*32; idx += 256)
            wsq[(idx >> 5)*33 + (idx & 31)] = in_w[l*96*32 + idx];
        for (int idx = t; idx < 1024; idx += 256)
            ow[(idx >> 5)*33 + (idx & 31)] = out_w[l*1024 + idx];
        __syncthreads();

        float* qk = g_qkvbuf[l & 1];
        if (t < 96) {
            float acc = in_b[l*96 + t];
#pragma unroll
            for (int d = 0; d < 32; d++) acc = fmaf(xv[d], wsq[t*33 + d], acc);
            qk[tau*96 + t] = acc;
        }
        grid_bar(l + 1);

        if (wid < 4) {
            int h = wid;
            float4 qa = *(const float4*)(qk + tau*96 + h*8);
            float4 qb = *(const float4*)(qk + tau*96 + h*8 + 4);
            int s0 = lane, s1 = lane + 32;
            const float* k0 = qk + (s0*2 + b)*96 + 32 + h*8;
            float4 ka = *(const float4*)(k0);
            float4 kb = *(const float4*)(k0 + 4);
            float sc0 = (qa.x*ka.x + qa.y*ka.y + qa.z*ka.z + qa.w*ka.w +
                         qb.x*kb.x + qb.y*kb.y + qb.z*kb.z + qb.w*kb.w) * 0.35355339059327373f;
            const float* v0p = qk + (s0*2 + b)*96 + 64 + h*8;
            float4 va = *(const float4*)(v0p);
            float4 vb = *(const float4*)(v0p + 4);
            float sc1 = -1e30f;
            float4 wa = make_float4(0.f,0.f,0.f,0.f), wb = wa;
            if (s1 < T_) {
                const float* k1 = qk + (s1*2 + b)*96 + 32 + h*8;
                float4 kc = *(const float4*)(k1);
                float4 kd = *(const float4*)(k1 + 4);
                sc1 = (qa.x*kc.x + qa.y*kc.y + qa.z*kc.z + qa.w*kc.w +
                       qb.x*kd.x + qb.y*kd.y + qb.z*kd.z + qb.w*kd.w) * 0.35355339059327373f;
                const float* v1p = qk + (s1*2 + b)*96 + 64 + h*8;
                wa = *(const float4*)(v1p);
                wb = *(const float4*)(v1p + 4);
            }
            float mx = warp_max(fmaxf(sc0, sc1));
            float p0 = expf(sc0 - mx);
            float p1 = (s1 < T_) ? expf(sc1 - mx) : 0.f;
            float sum = warp_sum(p0 + p1);
            float o[8];
            o[0] = p0*va.x + p1*wa.x;  o[1] = p0*va.y + p1*wa.y;
            o[2] = p0*va.z + p1*wa.z;  o[3] = p0*va.w + p1*wa.w;
            o[4] = p0*vb.x + p1*wb.x;  o[5] = p0*vb.y + p1*wb.y;
            o[6] = p0*vb.z + p1*wb.z;  o[7] = p0*vb.w + p1*wb.w;
#pragma unroll
            for (int e = 0; e < 8; e++) o[e] = warp_sum(o[e]);
            if (lane == 0) {
                float inv = 1.0f / sum;
#pragma unroll
                for (int e = 0; e < 8; e++) at[h*8 + e] = o[e] * inv;
            }
        }
        __syncthreads();

        if (t < 32) {
            float o = out_b[l*32 + t];
#pragma unroll
            for (int c = 0; c < 32; c++) o = fmaf(at[c], ow[t*33 + c], o);
            float val = xv[t] + o;
            float mean = warp_sum(val) * (1.0f/32.0f);
            float dvv = val - mean;
            float var = warp_sum(dvv*dvv) * (1.0f/32.0f);
            xs[t] = dvv * rsqrtf(var + 1e-5f) * ln1g[l*32 + t] + ln1b[l*32 + t];
        }
        __syncthreads();

        float4 xr[8];
#pragma unroll
        for (int i = 0; i < 8; i++) xr[i] = *(const float4*)(xs + i*4);
        const float* w1l = w1 + (size_t)l*1024*32;
        const float* b1l = b1 + l*1024;
#pragma unroll
        for (int i = 0; i < 4; i++) {
            int f = t*4 + i;
            float acc = b1l[f];
            const float4* wr = (const float4*)(w1l + (size_t)f*32);
#pragma unroll
            for (int d4 = 0; d4 < 8; d4++) {
                float4 w = wr[d4];
                float4 x = xr[d4];
                acc = fmaf(w.x, x.x, acc);
                acc = fmaf(w.y, x.y, acc);
                acc = fmaf(w.z, x.z, acc);
                acc = fmaf(w.w, x.w, acc);
            }
            gs[f] = 0.5f * acc * (1.0f + erff(acc * 0.70710678118654752f));
        }
        __syncthreads();
        const float* w2l = w2 + (size_t)l*32*1024;
#pragma unroll
        for (int pass = 0; pass < 4; pass++) {
            int d = pass*8 + wid;
            const float* wrow = w2l + (size_t)d*1024;
            float p = 0.f;
#pragma unroll 8
            for (int j = 0; j < 32; j++) p = fmaf(gs[j*32 + lane], wrow[j*32 + lane], p);
            p = warp_sum(p);
            if (lane == 0) ffo[d] = p;
        }
        __syncthreads();
        if (t < 32) {
            float val = xs[t] + ffo[t] + b2[l*32 + t];
            float mean = warp_sum(val) * (1.0f/32.0f);
            float dvv = val - mean;
            float var = warp_sum(dvv*dvv) * (1.0f/32.0f);
            xv[t] = dvv * rsqrtf(var + 1e-5f) * ln2g[l*32 + t] + ln2b[l*32 + t];
        }
        __syncthreads();
    }

    if (t < 32) {
        float y = xv[t];
        out[128 + tau*32 + t] = y;
        if (tau < 4) out[tau*32 + t] = y;
    }
}

// ---------------- launch ----------------
extern "C" void kernel_launch(void* const* d_in, const int* in_sizes, int n_in,
                              void* d_out, int out_size) {
    const float* v     = (const float*)d_in[0];
    const int*   edge  = (const int*)d_in[2];
    const float* W_emb = (const float*)d_in[3];
    const float* b_emb = (const float*)d_in[4];
    const float* W_g1  = (const float*)d_in[5];
    const float* b_g1  = (const float*)d_in[6];
    const float* W_g2  = (const float*)d_in[7];
    const float* b_g2  = (const float*)d_in[8];
    const float* W_fc  = (const float*)d_in[9];
    const float* b_fc  = (const float*)d_in[10];
    const float* muQ   = (const float*)d_in[11];
    const float* sigQ  = (const float*)d_in[12];
    const float* pe    = (const float*)d_in[13];
    const float* in_w  = (const float*)d_in[14];
    const float* in_b  = (const float*)d_in[15];
    const float* out_w = (const float*)d_in[16];
    const float* out_b = (const float*)d_in[17];
    const float* ln1g  = (const float*)d_in[18];
    const float* ln1b  = (const float*)d_in[19];
    const float* w1    = (const float*)d_in[20];
    const float* b1    = (const float*)d_in[21];
    const float* w2    = (const float*)d_in[22];
    const float* b2    = (const float*)d_in[23];
    const float* ln2g  = (const float*)d_in[24];
    const float* ln2b  = (const float*)d_in[25];

    k_prep<<<G_, 256>>>(edge, W_g2);                             // 0
    k_agg_gemm1<<<5000, 128>>>(v, W_emb, b_emb, W_g1, b_g1);     // 1
    k_agg128<<<5000, 256>>>();                                   // 2
    k_mma_gemm2pool<<<NT_, 256>>>(b_g2);                         // 3 <- ncu capture slot
    k_fc<<<G_, 256>>>(W_fc, b_fc, pe, muQ, sigQ);                // 4
    k_transformer<<<NB_, 256>>>(in_w, in_b, out_w, out_b, ln1g, ln1b,
                                w1, b1, w2, b2, ln2g, ln2b, (float*)d_out);  // 5
}

// round 13
// speedup vs baseline: 1.4838x; 1.1027x over previous
#include <cuda_runtime.h>
#include <cuda_bf16.h>
#include <math.h>
#include <stdint.h>

// ---------------- problem constants ----------------
#define G_  100        // B*S graphs
#define N_  2500       // nodes per graph
#define E_  7500       // edges per graph
#define TOT_NODES 250000
#define TOT_EDGES 750000
#define T_  52         // sequence length (S+2)
#define D_  32         // d_model
#define NB_ 104        // transformer blocks (tokens)
#define NT_ 3907       // ceil(250000/64) mma tiles
#define PAD_NODES (NT_*64)   // 250048 (tail tile reads padded region)

// ---------------- scratch (static, allocation-free) ----------------
__device__ float g_h1[TOT_NODES * 128];                 // 128 MB
__device__ unsigned short g_ahi[(size_t)PAD_NODES*128]; // 64 MB combined A, bf16 hi
__device__ unsigned short g_alo[(size_t)PAD_NODES*128]; // 64 MB combined A, bf16 lo
__device__ float g_dinv[TOT_NODES];
__device__ int   g_off[G_*(N_+1)];
__device__ int   g_rows[TOT_EDGES];
__device__ int   g_pool[G_*256];
__device__ float g_xseq[T_*2*D_];             // [t][b][d]
__device__ float g_qkvbuf[2][NB_*96];
__device__ int   g_bar_cnt;
__device__ volatile int g_bar_gen;
// bf16 hi/lo images of W_g2^T as [n][k], row stride 136 bf16 (68 words)
__device__ __align__(16) unsigned char g_wimg_hi[69632];
__device__ __align__(16) unsigned char g_wimg_lo[69632];

// ---------------- helpers ----------------
__device__ __forceinline__ float2 ffma2(float2 a, float2 b, float2 c) {
    union U { float2 f; unsigned long long u; } ua, ub, uc;
    ua.f = a; ub.f = b; uc.f = c;
    asm("fma.rn.f32x2 %0, %1, %2, %3;" : "=l"(uc.u) : "l"(ua.u), "l"(ub.u), "l"(uc.u));
    return uc.f;
}

__device__ __forceinline__ float warp_sum(float v) {
#pragma unroll
    for (int o = 16; o; o >>= 1) v += __shfl_xor_sync(0xffffffffu, v, o);
    return v;
}
__device__ __forceinline__ float warp_max(float v) {
#pragma unroll
    for (int o = 16; o; o >>= 1) v = fmaxf(v, __shfl_xor_sync(0xffffffffu, v, o));
    return v;
}

__device__ __forceinline__ float leaky(float x) {
    return x >= 0.0f ? x : 0.15f * x;
}

__device__ __forceinline__ int fkey(float f) {
    int i = __float_as_int(f);
    return i >= 0 ? i : (i ^ 0x7FFFFFFF);
}
__device__ __forceinline__ float fdec(int k) {
    return __int_as_float(k >= 0 ? k : (k ^ 0x7FFFFFFF));
}

// mma.sync m16n8k16 bf16 * bf16 -> f32 (baseline PTX; valid on sm_100 target)
__device__ __forceinline__ void mma_bf16(float* c, const uint32_t* a,
                                         uint32_t b0, uint32_t b1) {
    asm volatile(
        "mma.sync.aligned.m16n8k16.row.col.f32.bf16.bf16.f32 "
        "{%0,%1,%2,%3}, {%4,%5,%6,%7}, {%8,%9}, {%0,%1,%2,%3};"
        : "+f"(c[0]), "+f"(c[1]), "+f"(c[2]), "+f"(c[3])
        : "r"(a[0]), "r"(a[1]), "r"(a[2]), "r"(a[3]), "r"(b0), "r"(b1));
}

__device__ __forceinline__ void ldmat4(uint32_t* f, uint32_t addr) {
    asm volatile("ldmatrix.sync.aligned.m8n8.x4.shared.b16 {%0,%1,%2,%3}, [%4];"
                 : "=r"(f[0]), "=r"(f[1]), "=r"(f[2]), "=r"(f[3]) : "r"(addr));
}

// ---------------- fused graph prep (+ W_g2 bf16 image build) ----------------
__global__ __launch_bounds__(256) void k_prep(const int* __restrict__ edge,
                                              const float* __restrict__ W_g2) {
    __shared__ int cnt[N_];
    __shared__ int cur[N_];
    __shared__ int sm[256];
    int g = blockIdx.x;
    int t = threadIdx.x;
    for (int i = t; i < N_; i += 256) cnt[i] = 0;
    __syncthreads();

    const int2* eg = (const int2*)edge + (size_t)g * E_;
    for (int i = t; i < E_; i += 256) {
        int2 rc = eg[i];
        atomicAdd(&cnt[rc.y], 1);
    }
    __syncthreads();

    int base = t * 10;
    int loc[10];
    int s = 0;
    if (base < N_) {
#pragma unroll
        for (int i = 0; i < 10; i++) { loc[i] = cnt[base + i]; s += loc[i]; }
    }
    sm[t] = s;
    __syncthreads();
    for (int o = 1; o < 256; o <<= 1) {
        int vv = (t >= o) ? sm[t - o] : 0;
        __syncthreads();
        sm[t] += vv;
        __syncthreads();
    }
    int excl = sm[t] - s;
    if (base < N_) {
        int off = excl;
#pragma unroll
        for (int i = 0; i < 10; i++) {
            g_off[g*(N_+1) + base + i] = off;
            cur[base + i] = off;
            g_dinv[g*N_ + base + i] = rsqrtf((float)loc[i] + 1.0f);
            off += loc[i];
        }
    }
    if (t == 255) g_off[g*(N_+1) + N_] = sm[255];
    __syncthreads();

    for (int i = t; i < E_; i += 256) {
        int2 rc = eg[i];
        int pos = atomicAdd(&cur[rc.y], 1);
        g_rows[(size_t)g*E_ + pos] = rc.x;
    }

    g_pool[g*256 + t] = 0x80000000;
    if (g == 0 && t == 0) { g_bar_cnt = 0; g_bar_gen = 0; }

    // W image: B[n][k] = W_g2[k][n] as bf16 hi/lo, row stride 136 bf16
    for (int idx = g*256 + t; idx < 32768; idx += G_*256) {
        int k = idx >> 8, n = idx & 255;
        float w = W_g2[k*256 + n];
        __nv_bfloat16 hi = __float2bfloat16(w);
        __nv_bfloat16 lo = __float2bfloat16(w - __bfloat162float(hi));
        ((unsigned short*)g_wimg_hi)[n*136 + k] = __bfloat16_as_ushort(hi);
        ((unsigned short*)g_wimg_lo)[n*136 + k] = __bfloat16_as_ushort(lo);
    }
}

// nops: position ncu capture slot (4th launch) on k_agg_gemm1
__global__ void k_nop() {}

// ---------------- fused GCN layer 1: embed + aggregate + GEMM(64->128) ----------------
#define CAP1 320
__global__ __launch_bounds__(128) void k_agg_gemm1(
        const float* __restrict__ v, const float* __restrict__ W_emb,
        const float* __restrict__ b_emb, const float* __restrict__ W_g1,
        const float* __restrict__ b_g1) {
    __shared__ __align__(16) float As[64*56];
    __shared__ __align__(16) float4 ed_s[CAP1];
    __shared__ int   off_s[51];
    __shared__ float dnode[50];
    __shared__ float vself[50*3];
    int n0 = blockIdx.x * 50;
    int g = n0 / N_;
    int lnbase = n0 - g * N_;
    int t  = threadIdx.x;

    const float* dv = g_dinv + g*N_;
    const float* vg = v + (size_t)g * N_ * 3;
    if (t < 51) off_s[t] = g_off[g*(N_+1) + lnbase + t];
    if (t < 50) dnode[t] = dv[lnbase + t];
    for (int idx = t; idx < 150; idx += 128) vself[idx] = vg[(size_t)lnbase*3 + idx];
    __syncthreads();
    int e0 = off_s[0];
    int ecnt = off_s[50] - e0;
    const int* rowsg = g_rows + g*E_ + e0;
    for (int i = t; i < ecnt && i < CAP1; i += 128) {
        int r = rowsg[i];
        const float* vp = vg + (size_t)r*3;
        ed_s[i] = make_float4(vp[0], vp[1], vp[2], dv[r]);
    }
    __syncthreads();

    {
        int c = t & 63;
        int msub = t >> 6;
        float we0 = __ldg(W_emb + c), we1 = __ldg(W_emb + 64 + c);
        float we2 = __ldg(W_emb + 128 + c), be = __ldg(b_emb + c);
#pragma unroll 1
        for (int p = 0; p < 25; p++) {
            int m = p*2 + msub;
            float di = dnode[m];
            float xv = fmaxf(fmaf(vself[m*3+2], we2,
                         fmaf(vself[m*3+1], we1, fmaf(vself[m*3], we0, be))), 0.f);
            float acc = di * di * xv;
            int o0 = off_s[m] - e0, o1 = off_s[m+1] - e0;
            for (int e = o0; e < o1; e++) {
                float4 ed;
                if (e < CAP1) ed = ed_s[e];
                else {
                    int r = rowsg[e];
                    const float* vq = vg + (size_t)r*3;
                    ed = make_float4(vq[0], vq[1], vq[2], dv[r]);
                }
                float xn = fmaxf(fmaf(ed.z, we2, fmaf(ed.y, we1, fmaf(ed.x, we0, be))), 0.f);
                acc = fmaf(di * ed.w, xn, acc);
            }
            As[c*56 + m] = acc;
        }
    }
    __syncthreads();

    {
        int c4 = (t & 31) * 4;
        int mh = t >> 5;
        int mb = mh * 12;
        bool extra = (mh == 3);
        float2 acc[4][7];
#pragma unroll
        for (int j = 0; j < 4; j++)
#pragma unroll
            for (int q = 0; q < 7; q++) acc[j][q] = make_float2(0.f, 0.f);

        const float* Wp = W_g1 + c4;
#pragma unroll 2
        for (int k = 0; k < 64; k++) {
            float4 wv = __ldg((const float4*)(Wp + k*128));
            const float* arow = As + k*56 + mb;
            float4 a0 = *(const float4*)(arow);
            float4 a1 = *(const float4*)(arow + 4);
            float4 a2 = *(const float4*)(arow + 8);
            float wj[4] = {wv.x, wv.y, wv.z, wv.w};
#pragma unroll
            for (int j = 0; j < 4; j++) {
                float2 wp = make_float2(wj[j], wj[j]);
                acc[j][0] = ffma2(make_float2(a0.x, a0.y), wp, acc[j][0]);
                acc[j][1] = ffma2(make_float2(a0.z, a0.w), wp, acc[j][1]);
                acc[j][2] = ffma2(make_float2(a1.x, a1.y), wp, acc[j][2]);
                acc[j][3] = ffma2(make_float2(a1.z, a1.w), wp, acc[j][3]);
                acc[j][4] = ffma2(make_float2(a2.x, a2.y), wp, acc[j][4]);
                acc[j][5] = ffma2(make_float2(a2.z, a2.w), wp, acc[j][5]);
            }
            if (extra) {
                float2 a3 = *(const float2*)(arow + 12);
#pragma unroll
                for (int j = 0; j < 4; j++)
                    acc[j][6] = ffma2(a3, make_float2(wj[j], wj[j]), acc[j][6]);
            }
        }
        float4 bb = __ldg((const float4*)(b_g1 + c4));
        int pc = extra ? 7 : 6;
        for (int q = 0; q < pc; q++) {
            int m = mb + 2*q;
            float4 lo, hi;
            lo.x = leaky(acc[0][q].x + bb.x); lo.y = leaky(acc[1][q].x + bb.y);
            lo.z = leaky(acc[2][q].x + bb.z); lo.w = leaky(acc[3][q].x + bb.w);
            hi.x = leaky(acc[0][q].y + bb.x); hi.y = leaky(acc[1][q].y + bb.y);
            hi.z = leaky(acc[2][q].y + bb.z); hi.w = leaky(acc[3][q].y + bb.w);
            *(float4*)(g_h1 + (size_t)(n0 + m    )*128 + c4) = lo;
            *(float4*)(g_h1 + (size_t)(n0 + m + 1)*128 + c4) = hi;
        }
    }
}

// ---------------- layer-2 aggregation: edge gather + self term + bf16 split ----------------
// Writes combined As rows (h1a + d^2*h1) as packed bf16 hi/lo. Self values pre-staged in smem.
#define CAPA 320
__global__ __launch_bounds__(256) void k_agg128() {
    __shared__ __align__(8) float2 en_s[CAPA];
    __shared__ int   off_s[51];
    __shared__ float dnode[50];
    __shared__ float s_self[50*128];    // 25600 B
    int n0 = blockIdx.x * 50;
    int g = n0 / N_;
    int lnbase = n0 - g * N_;
    int t = threadIdx.x;

    const float* dv = g_dinv + g*N_;
    const float* h1g = g_h1 + (size_t)g * N_ * 128;
    if (t < 51) off_s[t] = g_off[g*(N_+1) + lnbase + t];
    if (t < 50) dnode[t] = dv[lnbase + t];
    // stage self rows
    for (int idx = t; idx < 50*128; idx += 256)
        s_self[idx] = g_h1[(size_t)(n0 + (idx >> 7))*128 + (idx & 127)];
    __syncthreads();
    int e0 = off_s[0];
    int ecnt = off_s[50] - e0;
    const int* rowsg = g_rows + g*E_ + e0;
    for (int i = t; i < ecnt && i < CAPA; i += 256) {
        int r = rowsg[i];
        en_s[i] = make_float2(__int_as_float(r), dv[r]);
    }
    __syncthreads();

    int c = t & 127;
    int msub = t >> 7;
    int mfirst = msub * 25;
    int O0 = off_s[mfirst] - e0;
    int O1 = off_s[mfirst + 25] - e0;
    size_t obase = (size_t)n0 * 128 + c;

    int m = mfirst;
    int nb = off_s[m + 1] - e0;
    float acc = 0.f;

    float va[4], wa[4];
#pragma unroll
    for (int i = 0; i < 4; i++) {
        int e = O0 + i;
        if (e < O1) {
            float2 en = (e < CAPA) ? en_s[e]
                      : make_float2(__int_as_float(rowsg[e]), dv[rowsg[e]]);
            wa[i] = en.y;
            va[i] = h1g[(size_t)__float_as_int(en.x) * 128 + c];
        }
    }
#pragma unroll 1
    for (int eb = O0; eb < O1; eb += 4) {
        float vb[4], wb[4];
#pragma unroll
        for (int i = 0; i < 4; i++) {
            int e = eb + 4 + i;
            if (e < O1) {
                float2 en = (e < CAPA) ? en_s[e]
                          : make_float2(__int_as_float(rowsg[e]), dv[rowsg[e]]);
                wb[i] = en.y;
                vb[i] = h1g[(size_t)__float_as_int(en.x) * 128 + c];
            }
        }
#pragma unroll
        for (int i = 0; i < 4; i++) {
            int e = eb + i;
            if (e < O1) {
                while (e == nb) {
                    float d = dnode[m];
                    float val = fmaf(d*d, s_self[m*128 + c], acc * d);
                    __nv_bfloat16 h = __float2bfloat16(val);
                    g_ahi[obase + (size_t)m*128] = __bfloat16_as_ushort(h);
                    g_alo[obase + (size_t)m*128] =
                        __bfloat16_as_ushort(__float2bfloat16(val - __bfloat162float(h)));
                    acc = 0.f;
                    m++;
                    nb = off_s[m + 1] - e0;
                }
                acc = fmaf(wa[i], va[i], acc);
            }
        }
#pragma unroll
        for (int i = 0; i < 4; i++) { va[i] = vb[i]; wa[i] = wb[i]; }
    }
    for (; m < mfirst + 25; m++) {
        float d = dnode[m];
        float val = fmaf(d*d, s_self[m*128 + c], acc * d);
        __nv_bfloat16 h = __float2bfloat16(val);
        g_ahi[obase + (size_t)m*128] = __bfloat16_as_ushort(h);
        g_alo[obase + (size_t)m*128] =
            __bfloat16_as_ushort(__float2bfloat16(val - __bfloat162float(h)));
        acc = 0.f;
    }
}

// ---------------- HMMA layer-2 GEMM(64x256x128, bf16x2-split) + max-pool ----------------
// A pre-split by k_agg128; staging is a pure copy. A fragments via ldmatrix.
__global__ __launch_bounds__(256, 2) void k_mma_gemm2pool(const float* __restrict__ b_g2) {
    __shared__ int s_pool[512];
    __shared__ float bias_s[256];
    __shared__ __align__(16) uint32_t Ah[64*68];   // 17408 B
    __shared__ __align__(16) uint32_t Al[64*68];   // 17408 B
    int n0 = blockIdx.x * 64;
    int t = threadIdx.x;
    int lane = t & 31, wid = t >> 5;
    int gq = lane >> 2, tq = lane & 3;
    int warpM = wid & 1, warpN = wid >> 1;

    s_pool[t] = 0x80000000;
    s_pool[t + 256] = 0x80000000;
    bias_s[t] = b_g2[t];

    // staging: copy pre-split A rows (padded arrays -> no tail branch)
#pragma unroll 1
    for (int idx = t; idx < 1024; idx += 256) {
        int m = idx >> 4;
        int q = idx & 15;           // 8 channels per chunk
        size_t goff = (size_t)(n0 + m)*128 + q*8;
        uint4 hv = *(const uint4*)(g_ahi + goff);
        uint4 lv = *(const uint4*)(g_alo + goff);
        *(uint4*)(Ah + m*68 + q*4) = hv;
        *(uint4*)(Al + m*68 + q*4) = lv;
    }
    __syncthreads();

    // ldmatrix lane addressing
    int tmat = lane >> 3, rr = lane & 7;
    uint32_t offw = (uint32_t)((warpM*32 + (tmat & 1)*8 + rr)*68 + (tmat >> 1)*4);
    uint32_t ah0 = (uint32_t)__cvta_generic_to_shared(Ah) + offw*4;
    uint32_t ah1 = ah0 + 16*68*4;
    uint32_t al0 = (uint32_t)__cvta_generic_to_shared(Al) + offw*4;
    uint32_t al1 = al0 + 16*68*4;

    const uint32_t* BhG = (const uint32_t*)g_wimg_hi;
    const uint32_t* BlG = (const uint32_t*)g_wimg_lo;
    float acc[2][8][4];
#pragma unroll
    for (int mt = 0; mt < 2; mt++)
#pragma unroll
        for (int nt = 0; nt < 8; nt++)
#pragma unroll
            for (int q = 0; q < 4; q++) acc[mt][nt][q] = 0.f;

#pragma unroll 1
    for (int ks = 0; ks < 8; ks++) {
        int kw = ks*8 + tq;
        uint32_t kb = (uint32_t)(ks*32);
        uint32_t fah[2][4], fal[2][4];
        ldmat4(fah[0], ah0 + kb);
        ldmat4(fah[1], ah1 + kb);
        ldmat4(fal[0], al0 + kb);
        ldmat4(fal[1], al1 + kb);
#pragma unroll
        for (int half = 0; half < 2; half++) {
            uint32_t bh[4][2], bl[4][2];
#pragma unroll
            for (int j = 0; j < 4; j++) {
                int n = warpN*64 + (half*4 + j)*8 + gq;
                bh[j][0] = __ldg(BhG + n*68 + kw);
                bh[j][1] = __ldg(BhG + n*68 + kw + 4);
                bl[j][0] = __ldg(BlG + n*68 + kw);
                bl[j][1] = __ldg(BlG + n*68 + kw + 4);
            }
#pragma unroll
            for (int j = 0; j < 4; j++) {
                int nt = half*4 + j;
#pragma unroll
                for (int mt = 0; mt < 2; mt++) {
                    mma_bf16(acc[mt][nt], fah[mt], bh[j][0], bh[j][1]);
                    mma_bf16(acc[mt][nt], fah[mt], bl[j][0], bl[j][1]);
                    mma_bf16(acc[mt][nt], fal[mt], bh[j][0], bh[j][1]);
                }
            }
        }
    }

    // epilogue: bias + leaky, per-graph masked max, smem pool
    int gA = n0 / N_;
    int gAend = (gA + 1) * N_;
    int lastn = n0 + 63;
    if (lastn >= TOT_NODES) lastn = TOT_NODES - 1;
    int gB = lastn / N_;
    bool straddle = (gB != gA);

#pragma unroll
    for (int nt = 0; nt < 8; nt++) {
        int col0 = warpN*64 + nt*8 + 2*tq;
        float b0 = bias_s[col0], b1 = bias_s[col0 + 1];
        float mA0 = -1e30f, mA1 = -1e30f, mB0 = -1e30f, mB1 = -1e30f;
#pragma unroll
        for (int mt = 0; mt < 2; mt++) {
#pragma unroll
            for (int hh = 0; hh < 2; hh++) {
                int r = warpM*32 + mt*16 + gq + 8*hh;
                int node = n0 + r;
                if (node < TOT_NODES) {
                    float v0 = leaky(acc[mt][nt][2*hh]     + b0);
                    float v1 = leaky(acc[mt][nt][2*hh + 1] + b1);
                    if (node < gAend) { mA0 = fmaxf(mA0, v0); mA1 = fmaxf(mA1, v1); }
                    else              { mB0 = fmaxf(mB0, v0); mB1 = fmaxf(mB1, v1); }
                }
            }
        }
#pragma unroll
        for (int o = 4; o < 32; o <<= 1) {
            mA0 = fmaxf(mA0, __shfl_xor_sync(0xffffffffu, mA0, o));
            mA1 = fmaxf(mA1, __shfl_xor_sync(0xffffffffu, mA1, o));
            if (straddle) {
                mB0 = fmaxf(mB0, __shfl_xor_sync(0xffffffffu, mB0, o));
                mB1 = fmaxf(mB1, __shfl_xor_sync(0xffffffffu, mB1, o));
            }
        }
        if (gq == 0) {
            atomicMax(&s_pool[col0],     fkey(mA0));
            atomicMax(&s_pool[col0 + 1], fkey(mA1));
            if (straddle) {
                atomicMax(&s_pool[256 + col0],     fkey(mB0));
                atomicMax(&s_pool[256 + col0 + 1], fkey(mB1));
            }
        }
    }
    __syncthreads();
    int pv = s_pool[t];
    if (pv != (int)0x80000000) atomicMax(&g_pool[gA*256 + t], pv);
    if (straddle) {
        int pb = s_pool[256 + t];
        if (pb != (int)0x80000000) atomicMax(&g_pool[gB*256 + t], pb);
    }
}

// decode pool, FC(256->32, relu) + pe; seeds mu/sigma rows. grid G_, 256 thr.
__global__ void k_fc(const float* __restrict__ W_fc, const float* __restrict__ b_fc,
                     const float* __restrict__ pe, const float* __restrict__ muQ,
                     const float* __restrict__ sigQ) {
    int g = blockIdx.x;
    int t = threadIdx.x;
    __shared__ float ps[256];
    ps[t] = fdec(g_pool[g*256 + t]);
    __syncthreads();
    if (t < 32) {
        float acc = b_fc[t];
        for (int k = 0; k < 256; k++) acc = fmaf(ps[k], W_fc[k*32 + t], acc);
        acc = fmaxf(acc, 0.0f);
        int b = g / 50, s = g - b*50;
        int tk = 2 + s;
        g_xseq[(tk*2 + b)*D_ + t] = acc + pe[tk*D_ + t];
    }
    if (g == 0 && t >= 128 && t < 256) {
        int i = t - 128;
        if (i < 128) {
            int tk = i >> 6;
            int bb = (i >> 5) & 1;
            int d = i & 31;
            g_xseq[(tk*2 + bb)*D_ + d] = (tk == 0 ? muQ[d] : sigQ[d]) + pe[tk*D_ + d];
        }
    }
}

// ---------------- single-kernel transformer ----------------
__device__ __forceinline__ void grid_bar(int target) {
    __syncthreads();
    if (threadIdx.x == 0) {
        __threadfence();
        int v = atomicAdd(&g_bar_cnt, 1);
        if (v + 1 == NB_ * target) {
            g_bar_gen = target;
        } else {
            while (g_bar_gen < target) { }
        }
        __threadfence();
    }
    __syncthreads();
}

__global__ __launch_bounds__(256) void k_transformer(
        const float* __restrict__ in_w, const float* __restrict__ in_b,
        const float* __restrict__ out_w, const float* __restrict__ out_b,
        const float* __restrict__ ln1g, const float* __restrict__ ln1b,
        const float* __restrict__ w1, const float* __restrict__ b1,
        const float* __restrict__ w2, const float* __restrict__ b2,
        const float* __restrict__ ln2g, const float* __restrict__ ln2b,
        float* __restrict__ out) {
    __shared__ float wsq[96*33];
    __shared__ float ow[32*33];
    __shared__ __align__(16) float xv[32];
    __shared__ float at[32];
    __shared__ __align__(16) float xs[32];
    __shared__ float gs[1024];
    __shared__ float ffo[32];
    int tau = blockIdx.x;
    int t = threadIdx.x;
    int wid = t >> 5, lane = t & 31;
    int b = tau & 1;

    if (t < 32) xv[t] = g_xseq[tau*32 + t];

    for (int l = 0; l < 4; l++) {
        for (int idx = t; idx < 96*32; idx += 256)
            wsq[(idx >> 5)*33 + (idx & 31)] = in_w[l*96*32 + idx];
        for (int idx = t; idx < 1024; idx += 256)
            ow[(idx >> 5)*33 + (idx & 31)] = out_w[l*1024 + idx];
        __syncthreads();

        float* qk = g_qkvbuf[l & 1];
        if (t < 96) {
            float acc = in_b[l*96 + t];
#pragma unroll
            for (int d = 0; d < 32; d++) acc = fmaf(xv[d], wsq[t*33 + d], acc);
            qk[tau*96 + t] = acc;
        }
        grid_bar(l + 1);

        if (wid < 4) {
            int h = wid;
            float4 qa = *(const float4*)(qk + tau*96 + h*8);
            float4 qb = *(const float4*)(qk + tau*96 + h*8 + 4);
            int s0 = lane, s1 = lane + 32;
            const float* k0 = qk + (s0*2 + b)*96 + 32 + h*8;
            float4 ka = *(const float4*)(k0);
            float4 kb = *(const float4*)(k0 + 4);
            float sc0 = (qa.x*ka.x + qa.y*ka.y + qa.z*ka.z + qa.w*ka.w +
                         qb.x*kb.x + qb.y*kb.y + qb.z*kb.z + qb.w*kb.w) * 0.35355339059327373f;
            const float* v0p = qk + (s0*2 + b)*96 + 64 + h*8;
            float4 va = *(const float4*)(v0p);
            float4 vb = *(const float4*)(v0p + 4);
            float sc1 = -1e30f;
            float4 wa = make_float4(0.f,0.f,0.f,0.f), wb = wa;
            if (s1 < T_) {
                const float* k1 = qk + (s1*2 + b)*96 + 32 + h*8;
                float4 kc = *(const float4*)(k1);
                float4 kd = *(const float4*)(k1 + 4);
                sc1 = (qa.x*kc.x + qa.y*kc.y + qa.z*kc.z + qa.w*kc.w +
                       qb.x*kd.x + qb.y*kd.y + qb.z*kd.z + qb.w*kd.w) * 0.35355339059327373f;
                const float* v1p = qk + (s1*2 + b)*96 + 64 + h*8;
                wa = *(const float4*)(v1p);
                wb = *(const float4*)(v1p + 4);
            }
            float mx = warp_max(fmaxf(sc0, sc1));
            float p0 = expf(sc0 - mx);
            float p1 = (s1 < T_) ? expf(sc1 - mx) : 0.f;
            float sum = warp_sum(p0 + p1);
            float o[8];
            o[0] = p0*va.x + p1*wa.x;  o[1] = p0*va.y + p1*wa.y;
            o[2] = p0*va.z + p1*wa.z;  o[3] = p0*va.w + p1*wa.w;
            o[4] = p0*vb.x + p1*wb.x;  o[5] = p0*vb.y + p1*wb.y;
            o[6] = p0*vb.z + p1*wb.z;  o[7] = p0*vb.w + p1*wb.w;
#pragma unroll
            for (int e = 0; e < 8; e++) o[e] = warp_sum(o[e]);
            if (lane == 0) {
                float inv = 1.0f / sum;
#pragma unroll
                for (int e = 0; e < 8; e++) at[h*8 + e] = o[e] * inv;
            }
        }
        __syncthreads();

        if (t < 32) {
            float o = out_b[l*32 + t];
#pragma unroll
            for (int c = 0; c < 32; c++) o = fmaf(at[c], ow[t*33 + c], o);
            float val = xv[t] + o;
            float mean = warp_sum(val) * (1.0f/32.0f);
            float dvv = val - mean;
            float var = warp_sum(dvv*dvv) * (1.0f/32.0f);
            xs[t] = dvv * rsqrtf(var + 1e-5f) * ln1g[l*32 + t] + ln1b[l*32 + t];
        }
        __syncthreads();

        float4 xr[8];
#pragma unroll
        for (int i = 0; i < 8; i++) xr[i] = *(const float4*)(xs + i*4);
        const float* w1l = w1 + (size_t)l*1024*32;
        const float* b1l = b1 + l*1024;
#pragma unroll
        for (int i = 0; i < 4; i++) {
            int f = t*4 + i;
            float acc = b1l[f];
            const float4* wr = (const float4*)(w1l + (size_t)f*32);
#pragma unroll
            for (int d4 = 0; d4 < 8; d4++) {
                float4 w = wr[d4];
                float4 x = xr[d4];
                acc = fmaf(w.x, x.x, acc);
                acc = fmaf(w.y, x.y, acc);
                acc = fmaf(w.z, x.z, acc);
                acc = fmaf(w.w, x.w, acc);
            }
            gs[f] = 0.5f * acc * (1.0f + erff(acc * 0.70710678118654752f));
        }
        __syncthreads();
        const float* w2l = w2 + (size_t)l*32*1024;
#pragma unroll
        for (int pass = 0; pass < 4; pass++) {
            int d = pass*8 + wid;
            const float* wrow = w2l + (size_t)d*1024;
            float p = 0.f;
#pragma unroll 8
            for (int j = 0; j < 32; j++) p = fmaf(gs[j*32 + lane], wrow[j*32 + lane], p);
            p = warp_sum(p);
            if (lane == 0) ffo[d] = p;
        }
        __syncthreads();
        if (t < 32) {
            float val = xs[t] + ffo[t] + b2[l*32 + t];
            float mean = warp_sum(val) * (1.0f/32.0f);
            float dvv = val - mean;
            float var = warp_sum(dvv*dvv) * (1.0f/32.0f);
            xv[t] = dvv * rsqrtf(var + 1e-5f) * ln2g[l*32 + t] + ln2b[l*32 + t];
        }
        __syncthreads();
    }

    if (t < 32) {
        float y = xv[t];
        out[128 + tau*32 + t] = y;
        if (tau < 4) out[tau*32 + t] = y;
    }
}

// ---------------- launch ----------------
extern "C" void kernel_launch(void* const* d_in, const int* in_sizes, int n_in,
                              void* d_out, int out_size) {
    const float* v     = (const float*)d_in[0];
    const int*   edge  = (const int*)d_in[2];
    const float* W_emb = (const float*)d_in[3];
    const float* b_emb = (const float*)d_in[4];
    const float* W_g1  = (const float*)d_in[5];
    const float* b_g1  = (const float*)d_in[6];
    const float* W_g2  = (const float*)d_in[7];
    const float* b_g2  = (const float*)d_in[8];
    const float* W_fc  = (const float*)d_in[9];
    const float* b_fc  = (const float*)d_in[10];
    const float* muQ   = (const float*)d_in[11];
    const float* sigQ  = (const float*)d_in[12];
    const float* pe    = (const float*)d_in[13];
    const float* in_w  = (const float*)d_in[14];
    const float* in_b  = (const float*)d_in[15];
    const float* out_w = (const float*)d_in[16];
    const float* out_b = (const float*)d_in[17];
    const float* ln1g  = (const float*)d_in[18];
    const float* ln1b  = (const float*)d_in[19];
    const float* w1    = (const float*)d_in[20];
    const float* b1    = (const float*)d_in[21];
    const float* w2    = (const float*)d_in[22];
    const float* b2    = (const float*)d_in[23];
    const float* ln2g  = (const float*)d_in[24];
    const float* ln2b  = (const float*)d_in[25];

    k_prep<<<G_, 256>>>(edge, W_g2);                             // 0
    k_nop<<<1, 32>>>();                                          // 1
    k_nop<<<1, 32>>>();                                          // 2
    k_agg_gemm1<<<5000, 128>>>(v, W_emb, b_emb, W_g1, b_g1);     // 3 <- ncu capture slot
    k_agg128<<<5000, 256>>>();                                   // 4
    k_mma_gemm2pool<<<NT_, 256>>>(b_g2);                         // 5
    k_fc<<<G_, 256>>>(W_fc, b_fc, pe, muQ, sigQ);                // 6
    k_transformer<<<NB_, 256>>>(in_w, in_b, out_w, out_b, ln1g, ln1b,
                                w1, b1, w2, b2, ln2g, ln2b, (float*)d_out);  // 7
}

// round 14
// speedup vs baseline: 1.5129x; 1.0196x over previous
#include <cuda_runtime.h>
#include <cuda_bf16.h>
#include <math.h>
#include <stdint.h>

// ---------------- problem constants ----------------
#define G_  100        // B*S graphs
#define N_  2500       // nodes per graph
#define E_  7500       // edges per graph
#define TOT_NODES 250000
#define TOT_EDGES 750000
#define T_  52         // sequence length (S+2)
#define D_  32         // d_model
#define NB_ 104        // transformer blocks (tokens)
#define NT_ 3907       // ceil(250000/64) mma tiles
#define PAD_NODES (NT_*64)   // 250048

// ---------------- scratch (static, allocation-free) ----------------
__device__ float g_h1[TOT_NODES * 128];                 // 128 MB
__device__ unsigned short g_ahi[(size_t)PAD_NODES*128]; // 64 MB combined A, bf16 hi
__device__ unsigned short g_alo[(size_t)PAD_NODES*128]; // 64 MB combined A, bf16 lo
__device__ float g_dinv[TOT_NODES];
__device__ int   g_off[G_*(N_+1)];
__device__ int   g_rows[TOT_EDGES];
__device__ int   g_pool[G_*256];
__device__ float g_xseq[T_*2*D_];             // [t][b][d]
__device__ float g_qkvbuf[2][NB_*96];
__device__ int   g_bar_cnt;
__device__ volatile int g_bar_gen;
// bf16 hi/lo images of W_g2^T as [n][k], row stride 136 bf16 (68 words)
__device__ __align__(16) unsigned char g_wimg_hi[69632];
__device__ __align__(16) unsigned char g_wimg_lo[69632];
// bf16 hi/lo images of W_g1^T as [n=128][k=64], row stride 72 bf16 (36 words)
__device__ __align__(16) uint32_t g_w1img_hi[128*36];
__device__ __align__(16) uint32_t g_w1img_lo[128*36];

// ---------------- helpers ----------------
__device__ __forceinline__ float warp_sum(float v) {
#pragma unroll
    for (int o = 16; o; o >>= 1) v += __shfl_xor_sync(0xffffffffu, v, o);
    return v;
}
__device__ __forceinline__ float warp_max(float v) {
#pragma unroll
    for (int o = 16; o; o >>= 1) v = fmaxf(v, __shfl_xor_sync(0xffffffffu, v, o));
    return v;
}

__device__ __forceinline__ float leaky(float x) {
    return x >= 0.0f ? x : 0.15f * x;
}

__device__ __forceinline__ int fkey(float f) {
    int i = __float_as_int(f);
    return i >= 0 ? i : (i ^ 0x7FFFFFFF);
}
__device__ __forceinline__ float fdec(int k) {
    return __int_as_float(k >= 0 ? k : (k ^ 0x7FFFFFFF));
}

// mma.sync m16n8k16 bf16 * bf16 -> f32
__device__ __forceinline__ void mma_bf16(float* c, const uint32_t* a,
                                         uint32_t b0, uint32_t b1) {
    asm volatile(
        "mma.sync.aligned.m16n8k16.row.col.f32.bf16.bf16.f32 "
        "{%0,%1,%2,%3}, {%4,%5,%6,%7}, {%8,%9}, {%0,%1,%2,%3};"
        : "+f"(c[0]), "+f"(c[1]), "+f"(c[2]), "+f"(c[3])
        : "r"(a[0]), "r"(a[1]), "r"(a[2]), "r"(a[3]), "r"(b0), "r"(b1));
}

__device__ __forceinline__ void ldmat4(uint32_t* f, uint32_t addr) {
    asm volatile("ldmatrix.sync.aligned.m8n8.x4.shared.b16 {%0,%1,%2,%3}, [%4];"
                 : "=r"(f[0]), "=r"(f[1]), "=r"(f[2]), "=r"(f[3]) : "r"(addr));
}

// ---------------- fused graph prep (+ W image builds) ----------------
__global__ __launch_bounds__(256) void k_prep(const int* __restrict__ edge,
                                              const float* __restrict__ W_g2,
                                              const float* __restrict__ W_g1) {
    __shared__ int cnt[N_];
    __shared__ int cur[N_];
    __shared__ int sm[256];
    int g = blockIdx.x;
    int t = threadIdx.x;
    for (int i = t; i < N_; i += 256) cnt[i] = 0;
    __syncthreads();

    const int2* eg = (const int2*)edge + (size_t)g * E_;
    for (int i = t; i < E_; i += 256) {
        int2 rc = eg[i];
        atomicAdd(&cnt[rc.y], 1);
    }
    __syncthreads();

    int base = t * 10;
    int loc[10];
    int s = 0;
    if (base < N_) {
#pragma unroll
        for (int i = 0; i < 10; i++) { loc[i] = cnt[base + i]; s += loc[i]; }
    }
    sm[t] = s;
    __syncthreads();
    for (int o = 1; o < 256; o <<= 1) {
        int vv = (t >= o) ? sm[t - o] : 0;
        __syncthreads();
        sm[t] += vv;
        __syncthreads();
    }
    int excl = sm[t] - s;
    if (base < N_) {
        int off = excl;
#pragma unroll
        for (int i = 0; i < 10; i++) {
            g_off[g*(N_+1) + base + i] = off;
            cur[base + i] = off;
            g_dinv[g*N_ + base + i] = rsqrtf((float)loc[i] + 1.0f);
            off += loc[i];
        }
    }
    if (t == 255) g_off[g*(N_+1) + N_] = sm[255];
    __syncthreads();

    for (int i = t; i < E_; i += 256) {
        int2 rc = eg[i];
        int pos = atomicAdd(&cur[rc.y], 1);
        g_rows[(size_t)g*E_ + pos] = rc.x;
    }

    g_pool[g*256 + t] = 0x80000000;
    if (g == 0 && t == 0) { g_bar_cnt = 0; g_bar_gen = 0; }

    // W_g2 image: B[n][k], stride 136 bf16
    for (int idx = g*256 + t; idx < 32768; idx += G_*256) {
        int k = idx >> 8, n = idx & 255;
        float w = W_g2[k*256 + n];
        __nv_bfloat16 hi = __float2bfloat16(w);
        __nv_bfloat16 lo = __float2bfloat16(w - __bfloat162float(hi));
        ((unsigned short*)g_wimg_hi)[n*136 + k] = __bfloat16_as_ushort(hi);
        ((unsigned short*)g_wimg_lo)[n*136 + k] = __bfloat16_as_ushort(lo);
    }
    // W_g1 image: B[n=128][k=64], stride 72 bf16
    for (int idx = g*256 + t; idx < 8192; idx += G_*256) {
        int k = idx >> 7, n = idx & 127;
        float w = W_g1[k*128 + n];
        __nv_bfloat16 hi = __float2bfloat16(w);
        __nv_bfloat16 lo = __float2bfloat16(w - __bfloat162float(hi));
        ((unsigned short*)g_w1img_hi)[n*72 + k] = __bfloat16_as_ushort(hi);
        ((unsigned short*)g_w1img_lo)[n*72 + k] = __bfloat16_as_ushort(lo);
    }
}

// nop: position ncu capture slot (4th launch) on k_agg128
__global__ void k_nop() {}

// ---------------- fused GCN layer 1: embed + aggregate + HMMA GEMM(64->128) ----------------
// 50 nodes/block (M padded to 64), 128 threads (2Mx2N warps). Stage 1 writes
// bf16 hi/lo A rows directly ([m][k], stride 36 words). B (W_g1 image) from L2.
#define CAP1 320
__global__ __launch_bounds__(128) void k_agg_gemm1(
        const float* __restrict__ v, const float* __restrict__ W_emb,
        const float* __restrict__ b_emb, const float* __restrict__ b_g1) {
    __shared__ __align__(16) uint32_t Ah[64*36];   // 9216 B
    __shared__ __align__(16) uint32_t Al[64*36];   // 9216 B
    __shared__ __align__(16) float4 ed_s[CAP1];
    __shared__ int   off_s[51];
    __shared__ float dnode[50];
    __shared__ float vself[50*3];
    int n0 = blockIdx.x * 50;
    int g = n0 / N_;
    int lnbase = n0 - g * N_;
    int t  = threadIdx.x;
    int lane = t & 31, wid = t >> 5;

    const float* dv = g_dinv + g*N_;
    const float* vg = v + (size_t)g * N_ * 3;
    if (t < 51) off_s[t] = g_off[g*(N_+1) + lnbase + t];
    if (t < 50) dnode[t] = dv[lnbase + t];
    for (int idx = t; idx < 150; idx += 128) vself[idx] = vg[(size_t)lnbase*3 + idx];
    // zero pad rows m=50..63
    for (int idx = t; idx < 14*36; idx += 128) {
        Ah[50*36 + idx] = 0;
        Al[50*36 + idx] = 0;
    }
    __syncthreads();
    int e0 = off_s[0];
    int ecnt = off_s[50] - e0;
    const int* rowsg = g_rows + g*E_ + e0;
    for (int i = t; i < ecnt && i < CAP1; i += 128) {
        int r = rowsg[i];
        const float* vp = vg + (size_t)r*3;
        ed_s[i] = make_float4(vp[0], vp[1], vp[2], dv[r]);
    }
    __syncthreads();

    // stage 1: A[m][c] = (A_hat relu(emb(v)))[n0+m][c], written as bf16 hi/lo
    {
        int c = t & 63;
        int msub = t >> 6;
        float we0 = __ldg(W_emb + c), we1 = __ldg(W_emb + 64 + c);
        float we2 = __ldg(W_emb + 128 + c), be = __ldg(b_emb + c);
        unsigned short* AhU = (unsigned short*)Ah;
        unsigned short* AlU = (unsigned short*)Al;
#pragma unroll 1
        for (int p = 0; p < 25; p++) {
            int m = p*2 + msub;
            float di = dnode[m];
            float xv = fmaxf(fmaf(vself[m*3+2], we2,
                         fmaf(vself[m*3+1], we1, fmaf(vself[m*3], we0, be))), 0.f);
            float acc = di * di * xv;
            int o0 = off_s[m] - e0, o1 = off_s[m+1] - e0;
            for (int e = o0; e < o1; e++) {
                float4 ed;
                if (e < CAP1) ed = ed_s[e];
                else {
                    int r = rowsg[e];
                    const float* vq = vg + (size_t)r*3;
                    ed = make_float4(vq[0], vq[1], vq[2], dv[r]);
                }
                float xn = fmaxf(fmaf(ed.z, we2, fmaf(ed.y, we1, fmaf(ed.x, we0, be))), 0.f);
                acc = fmaf(di * ed.w, xn, acc);
            }
            __nv_bfloat16 h = __float2bfloat16(acc);
            AhU[m*72 + c] = __bfloat16_as_ushort(h);
            AlU[m*72 + c] = __bfloat16_as_ushort(__float2bfloat16(acc - __bfloat162float(h)));
        }
    }
    __syncthreads();

    // stage 2: HMMA 64x128x64, bf16x2-split, B from L2
    {
        int gq = lane >> 2, tq = lane & 3;
        int warpM = wid & 1, warpN = wid >> 1;   // warpN in {0,1}, 64 cols each
        int tmat = lane >> 3, rr = lane & 7;
        uint32_t offw = (uint32_t)((warpM*32 + (tmat & 1)*8 + rr)*36 + (tmat >> 1)*4);
        uint32_t ah0 = (uint32_t)__cvta_generic_to_shared(Ah) + offw*4;
        uint32_t ah1 = ah0 + 16*36*4;
        uint32_t al0 = (uint32_t)__cvta_generic_to_shared(Al) + offw*4;
        uint32_t al1 = al0 + 16*36*4;

        const uint32_t* BhG = g_w1img_hi;
        const uint32_t* BlG = g_w1img_lo;
        float acc[2][8][4];
#pragma unroll
        for (int mt = 0; mt < 2; mt++)
#pragma unroll
            for (int nt = 0; nt < 8; nt++)
#pragma unroll
                for (int q = 0; q < 4; q++) acc[mt][nt][q] = 0.f;

#pragma unroll
        for (int ks = 0; ks < 4; ks++) {
            int kw = ks*8 + tq;
            uint32_t kb = (uint32_t)(ks*32);
            uint32_t fah[2][4], fal[2][4];
            ldmat4(fah[0], ah0 + kb);
            ldmat4(fah[1], ah1 + kb);
            ldmat4(fal[0], al0 + kb);
            ldmat4(fal[1], al1 + kb);
#pragma unroll
            for (int half = 0; half < 2; half++) {
                uint32_t bh[4][2], bl[4][2];
#pragma unroll
                for (int j = 0; j < 4; j++) {
                    int n = warpN*64 + (half*4 + j)*8 + gq;
                    bh[j][0] = __ldg(BhG + n*36 + kw);
                    bh[j][1] = __ldg(BhG + n*36 + kw + 4);
                    bl[j][0] = __ldg(BlG + n*36 + kw);
                    bl[j][1] = __ldg(BlG + n*36 + kw + 4);
                }
#pragma unroll
                for (int j = 0; j < 4; j++) {
                    int nt = half*4 + j;
#pragma unroll
                    for (int mt = 0; mt < 2; mt++) {
                        mma_bf16(acc[mt][nt], fah[mt], bh[j][0], bh[j][1]);
                        mma_bf16(acc[mt][nt], fah[mt], bl[j][0], bl[j][1]);
                        mma_bf16(acc[mt][nt], fal[mt], bh[j][0], bh[j][1]);
                    }
                }
            }
        }

        // epilogue: bias + leaky -> g_h1 (rows m<50 only)
#pragma unroll
        for (int nt = 0; nt < 8; nt++) {
            int col0 = warpN*64 + nt*8 + 2*tq;
            float2 bb = __ldg((const float2*)(b_g1 + col0));
#pragma unroll
            for (int mt = 0; mt < 2; mt++) {
#pragma unroll
                for (int hh = 0; hh < 2; hh++) {
                    int r = warpM*32 + mt*16 + gq + 8*hh;
                    if (r < 50) {
                        float2 o;
                        o.x = leaky(acc[mt][nt][2*hh]     + bb.x);
                        o.y = leaky(acc[mt][nt][2*hh + 1] + bb.y);
                        *(float2*)(g_h1 + (size_t)(n0 + r)*128 + col0) = o;
                    }
                }
            }
        }
    }
}

// ---------------- layer-2 aggregation: edge gather + self term + bf16 split ----------------
#define CAPA 320
__global__ __launch_bounds__(256) void k_agg128() {
    __shared__ __align__(8) float2 en_s[CAPA];
    __shared__ int   off_s[51];
    __shared__ float dnode[50];
    __shared__ float s_self[50*128];    // 25600 B
    int n0 = blockIdx.x * 50;
    int g = n0 / N_;
    int lnbase = n0 - g * N_;
    int t = threadIdx.x;

    const float* dv = g_dinv + g*N_;
    const float* h1g = g_h1 + (size_t)g * N_ * 128;
    if (t < 51) off_s[t] = g_off[g*(N_+1) + lnbase + t];
    if (t < 50) dnode[t] = dv[lnbase + t];
    for (int idx = t; idx < 50*128; idx += 256)
        s_self[idx] = g_h1[(size_t)(n0 + (idx >> 7))*128 + (idx & 127)];
    __syncthreads();
    int e0 = off_s[0];
    int ecnt = off_s[50] - e0;
    const int* rowsg = g_rows + g*E_ + e0;
    for (int i = t; i < ecnt && i < CAPA; i += 256) {
        int r = rowsg[i];
        en_s[i] = make_float2(__int_as_float(r), dv[r]);
    }
    __syncthreads();

    int c = t & 127;
    int msub = t >> 7;
    int mfirst = msub * 25;
    int O0 = off_s[mfirst] - e0;
    int O1 = off_s[mfirst + 25] - e0;
    size_t obase = (size_t)n0 * 128 + c;

    int m = mfirst;
    int nb = off_s[m + 1] - e0;
    float acc = 0.f;

    float va[4], wa[4];
#pragma unroll
    for (int i = 0; i < 4; i++) {
        int e = O0 + i;
        if (e < O1) {
            float2 en = (e < CAPA) ? en_s[e]
                      : make_float2(__int_as_float(rowsg[e]), dv[rowsg[e]]);
            wa[i] = en.y;
            va[i] = h1g[(size_t)__float_as_int(en.x) * 128 + c];
        }
    }
#pragma unroll 1
    for (int eb = O0; eb < O1; eb += 4) {
        float vb[4], wb[4];
#pragma unroll
        for (int i = 0; i < 4; i++) {
            int e = eb + 4 + i;
            if (e < O1) {
                float2 en = (e < CAPA) ? en_s[e]
                          : make_float2(__int_as_float(rowsg[e]), dv[rowsg[e]]);
                wb[i] = en.y;
                vb[i] = h1g[(size_t)__float_as_int(en.x) * 128 + c];
            }
        }
#pragma unroll
        for (int i = 0; i < 4; i++) {
            int e = eb + i;
            if (e < O1) {
                while (e == nb) {
                    float d = dnode[m];
                    float val = fmaf(d*d, s_self[m*128 + c], acc * d);
                    __nv_bfloat16 h = __float2bfloat16(val);
                    g_ahi[obase + (size_t)m*128] = __bfloat16_as_ushort(h);
                    g_alo[obase + (size_t)m*128] =
                        __bfloat16_as_ushort(__float2bfloat16(val - __bfloat162float(h)));
                    acc = 0.f;
                    m++;
                    nb = off_s[m + 1] - e0;
                }
                acc = fmaf(wa[i], va[i], acc);
            }
        }
#pragma unroll
        for (int i = 0; i < 4; i++) { va[i] = vb[i]; wa[i] = wb[i]; }
    }
    for (; m < mfirst + 25; m++) {
        float d = dnode[m];
        float val = fmaf(d*d, s_self[m*128 + c], acc * d);
        __nv_bfloat16 h = __float2bfloat16(val);
        g_ahi[obase + (size_t)m*128] = __bfloat16_as_ushort(h);
        g_alo[obase + (size_t)m*128] =
            __bfloat16_as_ushort(__float2bfloat16(val - __bfloat162float(h)));
        acc = 0.f;
    }
}

// ---------------- HMMA layer-2 GEMM(64x256x128, bf16x2-split) + max-pool ----------------
__global__ __launch_bounds__(256, 2) void k_mma_gemm2pool(const float* __restrict__ b_g2) {
    __shared__ int s_pool[512];
    __shared__ float bias_s[256];
    __shared__ __align__(16) uint32_t Ah[64*68];   // 17408 B
    __shared__ __align__(16) uint32_t Al[64*68];   // 17408 B
    int n0 = blockIdx.x * 64;
    int t = threadIdx.x;
    int lane = t & 31, wid = t >> 5;
    int gq = lane >> 2, tq = lane & 3;
    int warpM = wid & 1, warpN = wid >> 1;

    s_pool[t] = 0x80000000;
    s_pool[t + 256] = 0x80000000;
    bias_s[t] = b_g2[t];

#pragma unroll 1
    for (int idx = t; idx < 1024; idx += 256) {
        int m = idx >> 4;
        int q = idx & 15;
        size_t goff = (size_t)(n0 + m)*128 + q*8;
        uint4 hv = *(const uint4*)(g_ahi + goff);
        uint4 lv = *(const uint4*)(g_alo + goff);
        *(uint4*)(Ah + m*68 + q*4) = hv;
        *(uint4*)(Al + m*68 + q*4) = lv;
    }
    __syncthreads();

    int tmat = lane >> 3, rr = lane & 7;
    uint32_t offw = (uint32_t)((warpM*32 + (tmat & 1)*8 + rr)*68 + (tmat >> 1)*4);
    uint32_t ah0 = (uint32_t)__cvta_generic_to_shared(Ah) + offw*4;
    uint32_t ah1 = ah0 + 16*68*4;
    uint32_t al0 = (uint32_t)__cvta_generic_to_shared(Al) + offw*4;
    uint32_t al1 = al0 + 16*68*4;

    const uint32_t* BhG = (const uint32_t*)g_wimg_hi;
    const uint32_t* BlG = (const uint32_t*)g_wimg_lo;
    float acc[2][8][4];
#pragma unroll
    for (int mt = 0; mt < 2; mt++)
#pragma unroll
        for (int nt = 0; nt < 8; nt++)
#pragma unroll
            for (int q = 0; q < 4; q++) acc[mt][nt][q] = 0.f;

#pragma unroll 1
    for (int ks = 0; ks < 8; ks++) {
        int kw = ks*8 + tq;
        uint32_t kb = (uint32_t)(ks*32);
        uint32_t fah[2][4], fal[2][4];
        ldmat4(fah[0], ah0 + kb);
        ldmat4(fah[1], ah1 + kb);
        ldmat4(fal[0], al0 + kb);
        ldmat4(fal[1], al1 + kb);
#pragma unroll
        for (int half = 0; half < 2; half++) {
            uint32_t bh[4][2], bl[4][2];
#pragma unroll
            for (int j = 0; j < 4; j++) {
                int n = warpN*64 + (half*4 + j)*8 + gq;
                bh[j][0] = __ldg(BhG + n*68 + kw);
                bh[j][1] = __ldg(BhG + n*68 + kw + 4);
                bl[j][0] = __ldg(BlG + n*68 + kw);
                bl[j][1] = __ldg(BlG + n*68 + kw + 4);
            }
#pragma unroll
            for (int j = 0; j < 4; j++) {
                int nt = half*4 + j;
#pragma unroll
                for (int mt = 0; mt < 2; mt++) {
                    mma_bf16(acc[mt][nt], fah[mt], bh[j][0], bh[j][1]);
                    mma_bf16(acc[mt][nt], fah[mt], bl[j][0], bl[j][1]);
                    mma_bf16(acc[mt][nt], fal[mt], bh[j][0], bh[j][1]);
                }
            }
        }
    }

    int gA = n0 / N_;
    int gAend = (gA + 1) * N_;
    int lastn = n0 + 63;
    if (lastn >= TOT_NODES) lastn = TOT_NODES - 1;
    int gB = lastn / N_;
    bool straddle = (gB != gA);

#pragma unroll
    for (int nt = 0; nt < 8; nt++) {
        int col0 = warpN*64 + nt*8 + 2*tq;
        float b0 = bias_s[col0], b1 = bias_s[col0 + 1];
        float mA0 = -1e30f, mA1 = -1e30f, mB0 = -1e30f, mB1 = -1e30f;
#pragma unroll
        for (int mt = 0; mt < 2; mt++) {
#pragma unroll
            for (int hh = 0; hh < 2; hh++) {
                int r = warpM*32 + mt*16 + gq + 8*hh;
                int node = n0 + r;
                if (node < TOT_NODES) {
                    float v0 = leaky(acc[mt][nt][2*hh]     + b0);
                    float v1 = leaky(acc[mt][nt][2*hh + 1] + b1);
                    if (node < gAend) { mA0 = fmaxf(mA0, v0); mA1 = fmaxf(mA1, v1); }
                    else              { mB0 = fmaxf(mB0, v0); mB1 = fmaxf(mB1, v1); }
                }
            }
        }
#pragma unroll
        for (int o = 4; o < 32; o <<= 1) {
            mA0 = fmaxf(mA0, __shfl_xor_sync(0xffffffffu, mA0, o));
            mA1 = fmaxf(mA1, __shfl_xor_sync(0xffffffffu, mA1, o));
            if (straddle) {
                mB0 = fmaxf(mB0, __shfl_xor_sync(0xffffffffu, mB0, o));
                mB1 = fmaxf(mB1, __shfl_xor_sync(0xffffffffu, mB1, o));
            }
        }
        if (gq == 0) {
            atomicMax(&s_pool[col0],     fkey(mA0));
            atomicMax(&s_pool[col0 + 1], fkey(mA1));
            if (straddle) {
                atomicMax(&s_pool[256 + col0],     fkey(mB0));
                atomicMax(&s_pool[256 + col0 + 1], fkey(mB1));
            }
        }
    }
    __syncthreads();
    int pv = s_pool[t];
    if (pv != (int)0x80000000) atomicMax(&g_pool[gA*256 + t], pv);
    if (straddle) {
        int pb = s_pool[256 + t];
        if (pb != (int)0x80000000) atomicMax(&g_pool[gB*256 + t], pb);
    }
}

// decode pool, FC(256->32, relu) + pe; seeds mu/sigma rows. grid G_, 256 thr.
__global__ void k_fc(const float* __restrict__ W_fc, const float* __restrict__ b_fc,
                     const float* __restrict__ pe, const float* __restrict__ muQ,
                     const float* __restrict__ sigQ) {
    int g = blockIdx.x;
    int t = threadIdx.x;
    __shared__ float ps[256];
    ps[t] = fdec(g_pool[g*256 + t]);
    __syncthreads();
    if (t < 32) {
        float acc = b_fc[t];
        for (int k = 0; k < 256; k++) acc = fmaf(ps[k], W_fc[k*32 + t], acc);
        acc = fmaxf(acc, 0.0f);
        int b = g / 50, s = g - b*50;
        int tk = 2 + s;
        g_xseq[(tk*2 + b)*D_ + t] = acc + pe[tk*D_ + t];
    }
    if (g == 0 && t >= 128 && t < 256) {
        int i = t - 128;
        if (i < 128) {
            int tk = i >> 6;
            int bb = (i >> 5) & 1;
            int d = i & 31;
            g_xseq[(tk*2 + bb)*D_ + d] = (tk == 0 ? muQ[d] : sigQ[d]) + pe[tk*D_ + d];
        }
    }
}

// ---------------- single-kernel transformer ----------------
__device__ __forceinline__ void grid_bar(int target) {
    __syncthreads();
    if (threadIdx.x == 0) {
        __threadfence();
        int v = atomicAdd(&g_bar_cnt, 1);
        if (v + 1 == NB_ * target) {
            g_bar_gen = target;
        } else {
            while (g_bar_gen < target) { }
        }
        __threadfence();
    }
    __syncthreads();
}

__global__ __launch_bounds__(256) void k_transformer(
        const float* __restrict__ in_w, const float* __restrict__ in_b,
        const float* __restrict__ out_w, const float* __restrict__ out_b,
        const float* __restrict__ ln1g, const float* __restrict__ ln1b,
        const float* __restrict__ w1, const float* __restrict__ b1,
        const float* __restrict__ w2, const float* __restrict__ b2,
        const float* __restrict__ ln2g, const float* __restrict__ ln2b,
        float* __restrict__ out) {
    __shared__ float wsq[96*33];
    __shared__ float ow[32*33];
    __shared__ __align__(16) float xv[32];
    __shared__ float at[32];
    __shared__ __align__(16) float xs[32];
    __shared__ float gs[1024];
    __shared__ float ffo[32];
    int tau = blockIdx.x;
    int t = threadIdx.x;
    int wid = t >> 5, lane = t & 31;
    int b = tau & 1;

    if (t < 32) xv[t] = g_xseq[tau*32 + t];

    for (int l = 0; l < 4; l++) {
        for (int idx = t; idx < 96*32; idx += 256)
            wsq[(idx >> 5)*33 + (idx & 31)] = in_w[l*96*32 + idx];
        for (int idx = t; idx < 1024; idx += 256)
            ow[(idx >> 5)*33 + (idx & 31)] = out_w[l*1024 + idx];
        __syncthreads();

        float* qk = g_qkvbuf[l & 1];
        if (t < 96) {
            float acc = in_b[l*96 + t];
#pragma unroll
            for (int d = 0; d < 32; d++) acc = fmaf(xv[d], wsq[t*33 + d], acc);
            qk[tau*96 + t] = acc;
        }
        grid_bar(l + 1);

        if (wid < 4) {
            int h = wid;
            float4 qa = *(const float4*)(qk + tau*96 + h*8);
            float4 qb = *(const float4*)(qk + tau*96 + h*8 + 4);
            int s0 = lane, s1 = lane + 32;
            const float* k0 = qk + (s0*2 + b)*96 + 32 + h*8;
            float4 ka = *(const float4*)(k0);
            float4 kb = *(const float4*)(k0 + 4);
            float sc0 = (qa.x*ka.x + qa.y*ka.y + qa.z*ka.z + qa.w*ka.w +
                         qb.x*kb.x + qb.y*kb.y + qb.z*kb.z + qb.w*kb.w) * 0.35355339059327373f;
            const float* v0p = qk + (s0*2 + b)*96 + 64 + h*8;
            float4 va = *(const float4*)(v0p);
            float4 vb = *(const float4*)(v0p + 4);
            float sc1 = -1e30f;
            float4 wa = make_float4(0.f,0.f,0.f,0.f), wb = wa;
            if (s1 < T_) {
                const float* k1 = qk + (s1*2 + b)*96 + 32 + h*8;
                float4 kc = *(const float4*)(k1);
                float4 kd = *(const float4*)(k1 + 4);
                sc1 = (qa.x*kc.x + qa.y*kc.y + qa.z*kc.z + qa.w*kc.w +
                       qb.x*kd.x + qb.y*kd.y + qb.z*kd.z + qb.w*kd.w) * 0.35355339059327373f;
                const float* v1p = qk + (s1*2 + b)*96 + 64 + h*8;
                wa = *(const float4*)(v1p);
                wb = *(const float4*)(v1p + 4);
            }
            float mx = warp_max(fmaxf(sc0, sc1));
            float p0 = expf(sc0 - mx);
            float p1 = (s1 < T_) ? expf(sc1 - mx) : 0.f;
            float sum = warp_sum(p0 + p1);
            float o[8];
            o[0] = p0*va.x + p1*wa.x;  o[1] = p0*va.y + p1*wa.y;
            o[2] = p0*va.z + p1*wa.z;  o[3] = p0*va.w + p1*wa.w;
            o[4] = p0*vb.x + p1*wb.x;  o[5] = p0*vb.y + p1*wb.y;
            o[6] = p0*vb.z + p1*wb.z;  o[7] = p0*vb.w + p1*wb.w;
#pragma unroll
            for (int e = 0; e < 8; e++) o[e] = warp_sum(o[e]);
            if (lane == 0) {
                float inv = 1.0f / sum;
#pragma unroll
                for (int e = 0; e < 8; e++) at[h*8 + e] = o[e] * inv;
            }
        }
        __syncthreads();

        if (t < 32) {
            float o = out_b[l*32 + t];
#pragma unroll
            for (int c = 0; c < 32; c++) o = fmaf(at[c], ow[t*33 + c], o);
            float val = xv[t] + o;
            float mean = warp_sum(val) * (1.0f/32.0f);
            float dvv = val - mean;
            float var = warp_sum(dvv*dvv) * (1.0f/32.0f);
            xs[t] = dvv * rsqrtf(var + 1e-5f) * ln1g[l*32 + t] + ln1b[l*32 + t];
        }
        __syncthreads();

        float4 xr[8];
#pragma unroll
        for (int i = 0; i < 8; i++) xr[i] = *(const float4*)(xs + i*4);
        const float* w1l = w1 + (size_t)l*1024*32;
        const float* b1l = b1 + l*1024;
#pragma unroll
        for (int i = 0; i < 4; i++) {
            int f = t*4 + i;
            float acc = b1l[f];
            const float4* wr = (const float4*)(w1l + (size_t)f*32);
#pragma unroll
            for (int d4 = 0; d4 < 8; d4++) {
                float4 w = wr[d4];
                float4 x = xr[d4];
                acc = fmaf(w.x, x.x, acc);
                acc = fmaf(w.y, x.y, acc);
                acc = fmaf(w.z, x.z, acc);
                acc = fmaf(w.w, x.w, acc);
            }
            gs[f] = 0.5f * acc * (1.0f + erff(acc * 0.70710678118654752f));
        }
        __syncthreads();
        const float* w2l = w2 + (size_t)l*32*1024;
#pragma unroll
        for (int pass = 0; pass < 4; pass++) {
            int d = pass*8 + wid;
            const float* wrow = w2l + (size_t)d*1024;
            float p = 0.f;
#pragma unroll 8
            for (int j = 0; j < 32; j++) p = fmaf(gs[j*32 + lane], wrow[j*32 + lane], p);
            p = warp_sum(p);
            if (lane == 0) ffo[d] = p;
        }
        __syncthreads();
        if (t < 32) {
            float val = xs[t] + ffo[t] + b2[l*32 + t];
            float mean = warp_sum(val) * (1.0f/32.0f);
            float dvv = val - mean;
            float var = warp_sum(dvv*dvv) * (1.0f/32.0f);
            xv[t] = dvv * rsqrtf(var + 1e-5f) * ln2g[l*32 + t] + ln2b[l*32 + t];
        }
        __syncthreads();
    }

    if (t < 32) {
        float y = xv[t];
        out[128 + tau*32 + t] = y;
        if (tau < 4) out[tau*32 + t] = y;
    }
}

// ---------------- launch ----------------
extern "C" void kernel_launch(void* const* d_in, const int* in_sizes, int n_in,
                              void* d_out, int out_size) {
    const float* v     = (const float*)d_in[0];
    const int*   edge  = (const int*)d_in[2];
    const float* W_emb = (const float*)d_in[3];
    const float* b_emb = (const float*)d_in[4];
    const float* W_g1  = (const float*)d_in[5];
    const float* b_g1  = (const float*)d_in[6];
    const float* W_g2  = (const float*)d_in[7];
    const float* b_g2  = (const float*)d_in[8];
    const float* W_fc  = (const float*)d_in[9];
    const float* b_fc  = (const float*)d_in[10];
    const float* muQ   = (const float*)d_in[11];
    const float* sigQ  = (const float*)d_in[12];
    const float* pe    = (const float*)d_in[13];
    const float* in_w  = (const float*)d_in[14];
    const float* in_b  = (const float*)d_in[15];
    const float* out_w = (const float*)d_in[16];
    const float* out_b = (const float*)d_in[17];
    const float* ln1g  = (const float*)d_in[18];
    const float* ln1b  = (const float*)d_in[19];
    const float* w1    = (const float*)d_in[20];
    const float* b1    = (const float*)d_in[21];
    const float* w2    = (const float*)d_in[22];
    const float* b2    = (const float*)d_in[23];
    const float* ln2g  = (const float*)d_in[24];
    const float* ln2b  = (const float*)d_in[25];

    k_prep<<<G_, 256>>>(edge, W_g2, W_g1);                       // 0
    k_nop<<<1, 32>>>();                                          // 1
    k_agg_gemm1<<<5000, 128>>>(v, W_emb, b_emb, b_g1);           // 2
    k_agg128<<<5000, 256>>>();                                   // 3 <- ncu capture slot
    k_mma_gemm2pool<<<NT_, 256>>>(b_g2);                         // 4
    k_fc<<<G_, 256>>>(W_fc, b_fc, pe, muQ, sigQ);                // 5
    k_transformer<<<NB_, 256>>>(in_w, in_b, out_w, out_b, ln1g, ln1b,
                                w1, b1, w2, b2, ln2g, ln2b, (float*)d_out);  // 6
}

// round 16
// speedup vs baseline: 1.5903x; 1.0511x over previous
#include <cuda_runtime.h>
#include <cuda_bf16.h>
#include <math.h>
#include <stdint.h>

// ---------------- problem constants ----------------
#define G_  100        // B*S graphs
#define N_  2500       // nodes per graph
#define E_  7500       // edges per graph
#define TOT_NODES 250000
#define TOT_EDGES 750000
#define T_  52         // sequence length (S+2)
#define D_  32         // d_model
#define NB_ 104        // transformer blocks (tokens)
#define NT_ 3907       // ceil(250000/64) mma tiles
#define PAD_NODES (NT_*64)   // 250048

// ---------------- scratch (static, allocation-free) ----------------
__device__ float g_h1[TOT_NODES * 128];                 // 128 MB
__device__ unsigned short g_ahi[(size_t)PAD_NODES*128]; // 64 MB combined A, bf16 hi
__device__ unsigned short g_alo[(size_t)PAD_NODES*128]; // 64 MB combined A, bf16 lo
__device__ float g_dinv[TOT_NODES];
__device__ int   g_off[G_*(N_+1)];
__device__ int   g_rows[TOT_EDGES];
__device__ int   g_pool[G_*256];
__device__ float g_xseq[T_*2*D_];             // [t][b][d]
__device__ float g_qkvbuf[2][NB_*96];
__device__ int   g_bar_cnt;
__device__ volatile int g_bar_gen;
// bf16 hi/lo images of W_g2^T as [n][k], row stride 136 bf16 (68 words)
__device__ __align__(16) unsigned char g_wimg_hi[69632];
__device__ __align__(16) unsigned char g_wimg_lo[69632];
// bf16 hi/lo images of W_g1^T as [n=128][k=64], row stride 72 bf16 (36 words)
__device__ __align__(16) uint32_t g_w1img_hi[128*36];
__device__ __align__(16) uint32_t g_w1img_lo[128*36];

// ---------------- helpers ----------------
__device__ __forceinline__ float warp_sum(float v) {
#pragma unroll
    for (int o = 16; o; o >>= 1) v += __shfl_xor_sync(0xffffffffu, v, o);
    return v;
}
__device__ __forceinline__ float warp_max(float v) {
#pragma unroll
    for (int o = 16; o; o >>= 1) v = fmaxf(v, __shfl_xor_sync(0xffffffffu, v, o));
    return v;
}

__device__ __forceinline__ float leaky(float x) {
    return x >= 0.0f ? x : 0.15f * x;
}

__device__ __forceinline__ int fkey(float f) {
    int i = __float_as_int(f);
    return i >= 0 ? i : (i ^ 0x7FFFFFFF);
}
__device__ __forceinline__ float fdec(int k) {
    return __int_as_float(k >= 0 ? k : (k ^ 0x7FFFFFFF));
}

// mma.sync m16n8k16 bf16 * bf16 -> f32
__device__ __forceinline__ void mma_bf16(float* c, const uint32_t* a,
                                         uint32_t b0, uint32_t b1) {
    asm volatile(
        "mma.sync.aligned.m16n8k16.row.col.f32.bf16.bf16.f32 "
        "{%0,%1,%2,%3}, {%4,%5,%6,%7}, {%8,%9}, {%0,%1,%2,%3};"
        : "+f"(c[0]), "+f"(c[1]), "+f"(c[2]), "+f"(c[3])
        : "r"(a[0]), "r"(a[1]), "r"(a[2]), "r"(a[3]), "r"(b0), "r"(b1));
}

__device__ __forceinline__ void ldmat4(uint32_t* f, uint32_t addr) {
    asm volatile("ldmatrix.sync.aligned.m8n8.x4.shared.b16 {%0,%1,%2,%3}, [%4];"
                 : "=r"(f[0]), "=r"(f[1]), "=r"(f[2]), "=r"(f[3]) : "r"(addr));
}

// pack float4 -> bf16 hi/lo uint2 pair
__device__ __forceinline__ void split4(float4 v, uint2* hv, uint2* lv) {
    __nv_bfloat16 h0 = __float2bfloat16(v.x);
    __nv_bfloat16 h1 = __float2bfloat16(v.y);
    __nv_bfloat16 h2 = __float2bfloat16(v.z);
    __nv_bfloat16 h3 = __float2bfloat16(v.w);
    hv->x = (uint32_t)__bfloat16_as_ushort(h0) | ((uint32_t)__bfloat16_as_ushort(h1) << 16);
    hv->y = (uint32_t)__bfloat16_as_ushort(h2) | ((uint32_t)__bfloat16_as_ushort(h3) << 16);
    __nv_bfloat16 l0 = __float2bfloat16(v.x - __bfloat162float(h0));
    __nv_bfloat16 l1 = __float2bfloat16(v.y - __bfloat162float(h1));
    __nv_bfloat16 l2 = __float2bfloat16(v.z - __bfloat162float(h2));
    __nv_bfloat16 l3 = __float2bfloat16(v.w - __bfloat162float(h3));
    lv->x = (uint32_t)__bfloat16_as_ushort(l0) | ((uint32_t)__bfloat16_as_ushort(l1) << 16);
    lv->y = (uint32_t)__bfloat16_as_ushort(l2) | ((uint32_t)__bfloat16_as_ushort(l3) << 16);
}

// ---------------- fused graph prep (+ W image builds) ----------------
__global__ __launch_bounds__(256) void k_prep(const int* __restrict__ edge,
                                              const float* __restrict__ W_g2,
                                              const float* __restrict__ W_g1) {
    __shared__ int cnt[N_];
    __shared__ int cur[N_];
    __shared__ int sm[256];
    int g = blockIdx.x;
    int t = threadIdx.x;
    for (int i = t; i < N_; i += 256) cnt[i] = 0;
    __syncthreads();

    const int2* eg = (const int2*)edge + (size_t)g * E_;
    for (int i = t; i < E_; i += 256) {
        int2 rc = eg[i];
        atomicAdd(&cnt[rc.y], 1);
    }
    __syncthreads();

    int base = t * 10;
    int loc[10];
    int s = 0;
    if (base < N_) {
#pragma unroll
        for (int i = 0; i < 10; i++) { loc[i] = cnt[base + i]; s += loc[i]; }
    }
    sm[t] = s;
    __syncthreads();
    for (int o = 1; o < 256; o <<= 1) {
        int vv = (t >= o) ? sm[t - o] : 0;
        __syncthreads();
        sm[t] += vv;
        __syncthreads();
    }
    int excl = sm[t] - s;
    if (base < N_) {
        int off = excl;
#pragma unroll
        for (int i = 0; i < 10; i++) {
            g_off[g*(N_+1) + base + i] = off;
            cur[base + i] = off;
            g_dinv[g*N_ + base + i] = rsqrtf((float)loc[i] + 1.0f);
            off += loc[i];
        }
    }
    if (t == 255) g_off[g*(N_+1) + N_] = sm[255];
    __syncthreads();

    for (int i = t; i < E_; i += 256) {
        int2 rc = eg[i];
        int pos = atomicAdd(&cur[rc.y], 1);
        g_rows[(size_t)g*E_ + pos] = rc.x;
    }

    g_pool[g*256 + t] = 0x80000000;
    if (g == 0 && t == 0) { g_bar_cnt = 0; g_bar_gen = 0; }

    // W_g2 image: B[n][k], stride 136 bf16
    for (int idx = g*256 + t; idx < 32768; idx += G_*256) {
        int k = idx >> 8, n = idx & 255;
        float w = W_g2[k*256 + n];
        __nv_bfloat16 hi = __float2bfloat16(w);
        __nv_bfloat16 lo = __float2bfloat16(w - __bfloat162float(hi));
        ((unsigned short*)g_wimg_hi)[n*136 + k] = __bfloat16_as_ushort(hi);
        ((unsigned short*)g_wimg_lo)[n*136 + k] = __bfloat16_as_ushort(lo);
    }
    // W_g1 image: B[n=128][k=64], stride 72 bf16
    for (int idx = g*256 + t; idx < 8192; idx += G_*256) {
        int k = idx >> 7, n = idx & 127;
        float w = W_g1[k*128 + n];
        __nv_bfloat16 hi = __float2bfloat16(w);
        __nv_bfloat16 lo = __float2bfloat16(w - __bfloat162float(hi));
        ((unsigned short*)g_w1img_hi)[n*72 + k] = __bfloat16_as_ushort(hi);
        ((unsigned short*)g_w1img_lo)[n*72 + k] = __bfloat16_as_ushort(lo);
    }
}

// nop: position ncu capture slot (4th launch) on k_agg128
__global__ void k_nop() {}

// ---------------- fused GCN layer 1: embed + aggregate + HMMA GEMM(64->128) ----------------
#define CAP1 320
__global__ __launch_bounds__(128) void k_agg_gemm1(
        const float* __restrict__ v, const float* __restrict__ W_emb,
        const float* __restrict__ b_emb, const float* __restrict__ b_g1) {
    __shared__ __align__(16) uint32_t Ah[64*36];   // 9216 B
    __shared__ __align__(16) uint32_t Al[64*36];   // 9216 B
    __shared__ __align__(16) float4 ed_s[CAP1];
    __shared__ int   off_s[51];
    __shared__ float dnode[50];
    __shared__ float vself[50*3];
    int n0 = blockIdx.x * 50;
    int g = n0 / N_;
    int lnbase = n0 - g * N_;
    int t  = threadIdx.x;
    int lane = t & 31, wid = t >> 5;

    const float* dv = g_dinv + g*N_;
    const float* vg = v + (size_t)g * N_ * 3;
    if (t < 51) off_s[t] = g_off[g*(N_+1) + lnbase + t];
    if (t < 50) dnode[t] = dv[lnbase + t];
    for (int idx = t; idx < 150; idx += 128) vself[idx] = vg[(size_t)lnbase*3 + idx];
    for (int idx = t; idx < 14*36; idx += 128) {
        Ah[50*36 + idx] = 0;
        Al[50*36 + idx] = 0;
    }
    __syncthreads();
    int e0 = off_s[0];
    int ecnt = off_s[50] - e0;
    const int* rowsg = g_rows + g*E_ + e0;
    for (int i = t; i < ecnt && i < CAP1; i += 128) {
        int r = rowsg[i];
        const float* vp = vg + (size_t)r*3;
        ed_s[i] = make_float4(vp[0], vp[1], vp[2], dv[r]);
    }
    __syncthreads();

    // stage 1: A[m][c] bf16 hi/lo
    {
        int c = t & 63;
        int msub = t >> 6;
        float we0 = __ldg(W_emb + c), we1 = __ldg(W_emb + 64 + c);
        float we2 = __ldg(W_emb + 128 + c), be = __ldg(b_emb + c);
        unsigned short* AhU = (unsigned short*)Ah;
        unsigned short* AlU = (unsigned short*)Al;
#pragma unroll 1
        for (int p = 0; p < 25; p++) {
            int m = p*2 + msub;
            float di = dnode[m];
            float xv = fmaxf(fmaf(vself[m*3+2], we2,
                         fmaf(vself[m*3+1], we1, fmaf(vself[m*3], we0, be))), 0.f);
            float acc = di * di * xv;
            int o0 = off_s[m] - e0, o1 = off_s[m+1] - e0;
            for (int e = o0; e < o1; e++) {
                float4 ed;
                if (e < CAP1) ed = ed_s[e];
                else {
                    int r = rowsg[e];
                    const float* vq = vg + (size_t)r*3;
                    ed = make_float4(vq[0], vq[1], vq[2], dv[r]);
                }
                float xn = fmaxf(fmaf(ed.z, we2, fmaf(ed.y, we1, fmaf(ed.x, we0, be))), 0.f);
                acc = fmaf(di * ed.w, xn, acc);
            }
            __nv_bfloat16 h = __float2bfloat16(acc);
            AhU[m*72 + c] = __bfloat16_as_ushort(h);
            AlU[m*72 + c] = __bfloat16_as_ushort(__float2bfloat16(acc - __bfloat162float(h)));
        }
    }
    __syncthreads();

    // stage 2: HMMA 64x128x64
    {
        int gq = lane >> 2, tq = lane & 3;
        int warpM = wid & 1, warpN = wid >> 1;
        int tmat = lane >> 3, rr = lane & 7;
        uint32_t offw = (uint32_t)((warpM*32 + (tmat & 1)*8 + rr)*36 + (tmat >> 1)*4);
        uint32_t ah0 = (uint32_t)__cvta_generic_to_shared(Ah) + offw*4;
        uint32_t ah1 = ah0 + 16*36*4;
        uint32_t al0 = (uint32_t)__cvta_generic_to_shared(Al) + offw*4;
        uint32_t al1 = al0 + 16*36*4;

        const uint32_t* BhG = g_w1img_hi;
        const uint32_t* BlG = g_w1img_lo;
        float acc[2][8][4];
#pragma unroll
        for (int mt = 0; mt < 2; mt++)
#pragma unroll
            for (int nt = 0; nt < 8; nt++)
#pragma unroll
                for (int q = 0; q < 4; q++) acc[mt][nt][q] = 0.f;

#pragma unroll
        for (int ks = 0; ks < 4; ks++) {
            int kw = ks*8 + tq;
            uint32_t kb = (uint32_t)(ks*32);
            uint32_t fah[2][4], fal[2][4];
            ldmat4(fah[0], ah0 + kb);
            ldmat4(fah[1], ah1 + kb);
            ldmat4(fal[0], al0 + kb);
            ldmat4(fal[1], al1 + kb);
#pragma unroll
            for (int half = 0; half < 2; half++) {
                uint32_t bh[4][2], bl[4][2];
#pragma unroll
                for (int j = 0; j < 4; j++) {
                    int n = warpN*64 + (half*4 + j)*8 + gq;
                    bh[j][0] = __ldg(BhG + n*36 + kw);
                    bh[j][1] = __ldg(BhG + n*36 + kw + 4);
                    bl[j][0] = __ldg(BlG + n*36 + kw);
                    bl[j][1] = __ldg(BlG + n*36 + kw + 4);
                }
#pragma unroll
                for (int j = 0; j < 4; j++) {
                    int nt = half*4 + j;
#pragma unroll
                    for (int mt = 0; mt < 2; mt++) {
                        mma_bf16(acc[mt][nt], fah[mt], bh[j][0], bh[j][1]);
                        mma_bf16(acc[mt][nt], fah[mt], bl[j][0], bl[j][1]);
                        mma_bf16(acc[mt][nt], fal[mt], bh[j][0], bh[j][1]);
                    }
                }
            }
        }

#pragma unroll
        for (int nt = 0; nt < 8; nt++) {
            int col0 = warpN*64 + nt*8 + 2*tq;
            float2 bb = __ldg((const float2*)(b_g1 + col0));
#pragma unroll
            for (int mt = 0; mt < 2; mt++) {
#pragma unroll
                for (int hh = 0; hh < 2; hh++) {
                    int r = warpM*32 + mt*16 + gq + 8*hh;
                    if (r < 50) {
                        float2 o;
                        o.x = leaky(acc[mt][nt][2*hh]     + bb.x);
                        o.y = leaky(acc[mt][nt][2*hh + 1] + bb.y);
                        *(float2*)(g_h1 + (size_t)(n0 + r)*128 + col0) = o;
                    }
                }
            }
        }
    }
}

// ---------------- layer-2 aggregation: warp-per-node-group, lane = channel-quad ----------------
#define CAPA 320
__global__ __launch_bounds__(256) void k_agg128() {
    __shared__ __align__(8) float2 en_s[CAPA];
    __shared__ int   off_s[51];
    __shared__ float dnode[50];
    __shared__ __align__(16) float s_self[50*128];    // 25600 B
    int n0 = blockIdx.x * 50;
    int g = n0 / N_;
    int lnbase = n0 - g * N_;
    int t = threadIdx.x;
    int lane = t & 31, w = t >> 5;

    const float* dv = g_dinv + g*N_;
    const float* h1g = g_h1 + (size_t)g * N_ * 128;
    if (t < 51) off_s[t] = g_off[g*(N_+1) + lnbase + t];
    if (t < 50) dnode[t] = dv[lnbase + t];
    for (int idx = t; idx < 50*32; idx += 256)
        ((float4*)s_self)[idx] = *(const float4*)(g_h1 + (size_t)n0*128 + idx*4);
    __syncthreads();
    int e0 = off_s[0];
    int ecnt = off_s[50] - e0;
    const int* rowsg = g_rows + g*E_ + e0;
    for (int i = t; i < ecnt && i < CAPA; i += 256) {
        int r = rowsg[i];
        en_s[i] = make_float2(__int_as_float(r), dv[r]);
    }
    __syncthreads();

    int m0 = (w*50) >> 3;
    int m1 = ((w+1)*50) >> 3;
    int O0 = off_s[m0] - e0;
    int O1 = off_s[m1] - e0;
    int cq = lane * 4;
    size_t obase = (size_t)n0 * 128 + cq;

    int m = m0;
    int nb = off_s[m + 1] - e0;
    float4 acc = make_float4(0.f, 0.f, 0.f, 0.f);

    float4 va[4];
    float  wa[4];
#pragma unroll
    for (int i = 0; i < 4; i++) {
        int e = O0 + i;
        if (e < O1) {
            float2 en = (e < CAPA) ? en_s[e]
                      : make_float2(__int_as_float(rowsg[e]), dv[rowsg[e]]);
            wa[i] = en.y;
            va[i] = *(const float4*)(h1g + (size_t)__float_as_int(en.x)*128 + cq);
        }
    }
#pragma unroll 1
    for (int eb = O0; eb < O1; eb += 4) {
        float4 vb[4];
        float  wb[4];
#pragma unroll
        for (int i = 0; i < 4; i++) {
            int e = eb + 4 + i;
            if (e < O1) {
                float2 en = (e < CAPA) ? en_s[e]
                          : make_float2(__int_as_float(rowsg[e]), dv[rowsg[e]]);
                wb[i] = en.y;
                vb[i] = *(const float4*)(h1g + (size_t)__float_as_int(en.x)*128 + cq);
            }
        }
#pragma unroll
        for (int i = 0; i < 4; i++) {
            int e = eb + i;
            if (e < O1) {
                while (e == nb) {   // flush finished node(s) — warp-uniform
                    float d = dnode[m];
                    float4 sf = *(const float4*)(s_self + m*128 + cq);
                    float4 val;
                    val.x = fmaf(d*d, sf.x, acc.x * d);
                    val.y = fmaf(d*d, sf.y, acc.y * d);
                    val.z = fmaf(d*d, sf.z, acc.z * d);
                    val.w = fmaf(d*d, sf.w, acc.w * d);
                    uint2 hv, lv;
                    split4(val, &hv, &lv);
                    *(uint2*)(g_ahi + obase + (size_t)m*128) = hv;
                    *(uint2*)(g_alo + obase + (size_t)m*128) = lv;
                    acc = make_float4(0.f, 0.f, 0.f, 0.f);
                    m++;
                    nb = off_s[m + 1] - e0;
                }
                acc.x = fmaf(wa[i], va[i].x, acc.x);
                acc.y = fmaf(wa[i], va[i].y, acc.y);
                acc.z = fmaf(wa[i], va[i].z, acc.z);
                acc.w = fmaf(wa[i], va[i].w, acc.w);
            }
        }
#pragma unroll
        for (int i = 0; i < 4; i++) { va[i] = vb[i]; wa[i] = wb[i]; }
    }
    for (; m < m1; m++) {
        float d = dnode[m];
        float4 sf = *(const float4*)(s_self + m*128 + cq);
        float4 val;
        val.x = fmaf(d*d, sf.x, acc.x * d);
        val.y = fmaf(d*d, sf.y, acc.y * d);
        val.z = fmaf(d*d, sf.z, acc.z * d);
        val.w = fmaf(d*d, sf.w, acc.w * d);
        uint2 hv, lv;
        split4(val, &hv, &lv);
        *(uint2*)(g_ahi + obase + (size_t)m*128) = hv;
        *(uint2*)(g_alo + obase + (size_t)m*128) = lv;
        acc = make_float4(0.f, 0.f, 0.f, 0.f);
    }
}

// ---------------- HMMA layer-2 GEMM(64x256x128, bf16x2-split) + max-pool ----------------
__global__ __launch_bounds__(256, 2) void k_mma_gemm2pool(const float* __restrict__ b_g2) {
    __shared__ int s_pool[512];
    __shared__ float bias_s[256];
    __shared__ __align__(16) uint32_t Ah[64*68];   // 17408 B
    __shared__ __align__(16) uint32_t Al[64*68];   // 17408 B
    int n0 = blockIdx.x * 64;
    int t = threadIdx.x;
    int lane = t & 31, wid = t >> 5;
    int gq = lane >> 2, tq = lane & 3;
    int warpM = wid & 1, warpN = wid >> 1;

    s_pool[t] = 0x80000000;
    s_pool[t + 256] = 0x80000000;
    bias_s[t] = b_g2[t];

#pragma unroll 1
    for (int idx = t; idx < 1024; idx += 256) {
        int m = idx >> 4;
        int q = idx & 15;
        size_t goff = (size_t)(n0 + m)*128 + q*8;
        uint4 hv = *(const uint4*)(g_ahi + goff);
        uint4 lv = *(const uint4*)(g_alo + goff);
        *(uint4*)(Ah + m*68 + q*4) = hv;
        *(uint4*)(Al + m*68 + q*4) = lv;
    }
    __syncthreads();

    int tmat = lane >> 3, rr = lane & 7;
    uint32_t offw = (uint32_t)((warpM*32 + (tmat & 1)*8 + rr)*68 + (tmat >> 1)*4);
    uint32_t ah0 = (uint32_t)__cvta_generic_to_shared(Ah) + offw*4;
    uint32_t ah1 = ah0 + 16*68*4;
    uint32_t al0 = (uint32_t)__cvta_generic_to_shared(Al) + offw*4;
    uint32_t al1 = al0 + 16*68*4;

    const uint32_t* BhG = (const uint32_t*)g_wimg_hi;
    const uint32_t* BlG = (const uint32_t*)g_wimg_lo;
    float acc[2][8][4];
#pragma unroll
    for (int mt = 0; mt < 2; mt++)
#pragma unroll
        for (int nt = 0; nt < 8; nt++)
#pragma unroll
            for (int q = 0; q < 4; q++) acc[mt][nt][q] = 0.f;

#pragma unroll 1
    for (int ks = 0; ks < 8; ks++) {
        int kw = ks*8 + tq;
        uint32_t kb = (uint32_t)(ks*32);
        uint32_t fah[2][4], fal[2][4];
        ldmat4(fah[0], ah0 + kb);
        ldmat4(fah[1], ah1 + kb);
        ldmat4(fal[0], al0 + kb);
        ldmat4(fal[1], al1 + kb);
#pragma unroll
        for (int half = 0; half < 2; half++) {
            uint32_t bh[4][2], bl[4][2];
#pragma unroll
            for (int j = 0; j < 4; j++) {
                int n = warpN*64 + (half*4 + j)*8 + gq;
                bh[j][0] = __ldg(BhG + n*68 + kw);
                bh[j][1] = __ldg(BhG + n*68 + kw + 4);
                bl[j][0] = __ldg(BlG + n*68 + kw);
                bl[j][1] = __ldg(BlG + n*68 + kw + 4);
            }
#pragma unroll
            for (int j = 0; j < 4; j++) {
                int nt = half*4 + j;
#pragma unroll
                for (int mt = 0; mt < 2; mt++) {
                    mma_bf16(acc[mt][nt], fah[mt], bh[j][0], bh[j][1]);
                    mma_bf16(acc[mt][nt], fah[mt], bl[j][0], bl[j][1]);
                    mma_bf16(acc[mt][nt], fal[mt], bh[j][0], bh[j][1]);
                }
            }
        }
    }

    int gA = n0 / N_;
    int gAend = (gA + 1) * N_;
    int lastn = n0 + 63;
    if (lastn >= TOT_NODES) lastn = TOT_NODES - 1;
    int gB = lastn / N_;
    bool straddle = (gB != gA);

#pragma unroll
    for (int nt = 0; nt < 8; nt++) {
        int col0 = warpN*64 + nt*8 + 2*tq;
        float b0 = bias_s[col0], b1 = bias_s[col0 + 1];
        float mA0 = -1e30f, mA1 = -1e30f, mB0 = -1e30f, mB1 = -1e30f;
#pragma unroll
        for (int mt = 0; mt < 2; mt++) {
#pragma unroll
            for (int hh = 0; hh < 2; hh++) {
                int r = warpM*32 + mt*16 + gq + 8*hh;
                int node = n0 + r;
                if (node < TOT_NODES) {
                    float v0 = leaky(acc[mt][nt][2*hh]     + b0);
                    float v1 = leaky(acc[mt][nt][2*hh + 1] + b1);
                    if (node < gAend) { mA0 = fmaxf(mA0, v0); mA1 = fmaxf(mA1, v1); }
                    else              { mB0 = fmaxf(mB0, v0); mB1 = fmaxf(mB1, v1); }
                }
            }
        }
#pragma unroll
        for (int o = 4; o < 32; o <<= 1) {
            mA0 = fmaxf(mA0, __shfl_xor_sync(0xffffffffu, mA0, o));
            mA1 = fmaxf(mA1, __shfl_xor_sync(0xffffffffu, mA1, o));
            if (straddle) {
                mB0 = fmaxf(mB0, __shfl_xor_sync(0xffffffffu, mB0, o));
                mB1 = fmaxf(mB1, __shfl_xor_sync(0xffffffffu, mB1, o));
            }
        }
        if (gq == 0) {
            atomicMax(&s_pool[col0],     fkey(mA0));
            atomicMax(&s_pool[col0 + 1], fkey(mA1));
            if (straddle) {
                atomicMax(&s_pool[256 + col0],     fkey(mB0));
                atomicMax(&s_pool[256 + col0 + 1], fkey(mB1));
            }
        }
    }
    __syncthreads();
    int pv = s_pool[t];
    if (pv != (int)0x80000000) atomicMax(&g_pool[gA*256 + t], pv);
    if (straddle) {
        int pb = s_pool[256 + t];
        if (pb != (int)0x80000000) atomicMax(&g_pool[gB*256 + t], pb);
    }
}

// decode pool, FC(256->32, relu) + pe; seeds mu/sigma rows. grid G_, 256 thr.
__global__ void k_fc(const float* __restrict__ W_fc, const float* __restrict__ b_fc,
                     const float* __restrict__ pe, const float* __restrict__ muQ,
                     const float* __restrict__ sigQ) {
    int g = blockIdx.x;
    int t = threadIdx.x;
    __shared__ float ps[256];
    ps[t] = fdec(g_pool[g*256 + t]);
    __syncthreads();
    if (t < 32) {
        float acc = b_fc[t];
        for (int k = 0; k < 256; k++) acc = fmaf(ps[k], W_fc[k*32 + t], acc);
        acc = fmaxf(acc, 0.0f);
        int b = g / 50, s = g - b*50;
        int tk = 2 + s;
        g_xseq[(tk*2 + b)*D_ + t] = acc + pe[tk*D_ + t];
    }
    if (g == 0 && t >= 128 && t < 256) {
        int i = t - 128;
        if (i < 128) {
            int tk = i >> 6;
            int bb = (i >> 5) & 1;
            int d = i & 31;
            g_xseq[(tk*2 + bb)*D_ + d] = (tk == 0 ? muQ[d] : sigQ[d]) + pe[tk*D_ + d];
        }
    }
}

// ---------------- single-kernel transformer ----------------
__device__ __forceinline__ void grid_bar(int target) {
    __syncthreads();
    if (threadIdx.x == 0) {
        __threadfence();
        int v = atomicAdd(&g_bar_cnt, 1);
        if (v + 1 == NB_ * target) {
            g_bar_gen = target;
        } else {
            while (g_bar_gen < target) { }
        }
        __threadfence();
    }
    __syncthreads();
}

__global__ __launch_bounds__(256) void k_transformer(
        const float* __restrict__ in_w, const float* __restrict__ in_b,
        const float* __restrict__ out_w, const float* __restrict__ out_b,
        const float* __restrict__ ln1g, const float* __restrict__ ln1b,
        const float* __restrict__ w1, const float* __restrict__ b1,
        const float* __restrict__ w2, const float* __restrict__ b2,
        const float* __restrict__ ln2g, const float* __restrict__ ln2b,
        float* __restrict__ out) {
    __shared__ float wsq[96*33];
    __shared__ float ow[32*33];
    __shared__ __align__(16) float xv[32];
    __shared__ float at[32];
    __shared__ __align__(16) float xs[32];
    __shared__ float gs[1024];
    __shared__ float ffo[32];
    int tau = blockIdx.x;
    int t = threadIdx.x;
    int wid = t >> 5, lane = t & 31;
    int b = tau & 1;

    if (t < 32) xv[t] = g_xseq[tau*32 + t];

    for (int l = 0; l < 4; l++) {
        for (int idx = t; idx < 96*32; idx += 256)
            wsq[(idx >> 5)*33 + (idx & 31)] = in_w[l*96*32 + idx];
        for (int idx = t; idx < 1024; idx += 256)
            ow[(idx >> 5)*33 + (idx & 31)] = out_w[l*1024 + idx];
        __syncthreads();

        float* qk = g_qkvbuf[l & 1];
        if (t < 96) {
            float acc = in_b[l*96 + t];
#pragma unroll
            for (int d = 0; d < 32; d++) acc = fmaf(xv[d], wsq[t*33 + d], acc);
            qk[tau*96 + t] = acc;
        }
        grid_bar(l + 1);

        if (wid < 4) {
            int h = wid;
            float4 qa = *(const float4*)(qk + tau*96 + h*8);
            float4 qb = *(const float4*)(qk + tau*96 + h*8 + 4);
            int s0 = lane, s1 = lane + 32;
            const float* k0 = qk + (s0*2 + b)*96 + 32 + h*8;
            float4 ka = *(const float4*)(k0);
            float4 kb = *(const float4*)(k0 + 4);
            float sc0 = (qa.x*ka.x + qa.y*ka.y + qa.z*ka.z + qa.w*ka.w +
                         qb.x*kb.x + qb.y*kb.y + qb.z*kb.z + qb.w*kb.w) * 0.35355339059327373f;
            const float* v0p = qk + (s0*2 + b)*96 + 64 + h*8;
            float4 va = *(const float4*)(v0p);
            float4 vb = *(const float4*)(v0p + 4);
            float sc1 = -1e30f;
            float4 wa = make_float4(0.f,0.f,0.f,0.f), wb = wa;
            if (s1 < T_) {
                const float* k1 = qk + (s1*2 + b)*96 + 32 + h*8;
                float4 kc = *(const float4*)(k1);
                float4 kd = *(const float4*)(k1 + 4);
                sc1 = (qa.x*kc.x + qa.y*kc.y + qa.z*kc.z + qa.w*kc.w +
                       qb.x*kd.x + qb.y*kd.y + qb.z*kd.z + qb.w*kd.w) * 0.35355339059327373f;
                const float* v1p = qk + (s1*2 + b)*96 + 64 + h*8;
                wa = *(const float4*)(v1p);
                wb = *(const float4*)(v1p + 4);
            }
            float mx = warp_max(fmaxf(sc0, sc1));
            float p0 = expf(sc0 - mx);
            float p1 = (s1 < T_) ? expf(sc1 - mx) : 0.f;
            float sum = warp_sum(p0 + p1);
            float o[8];
            o[0] = p0*va.x + p1*wa.x;  o[1] = p0*va.y + p1*wa.y;
            o[2] = p0*va.z + p1*wa.z;  o[3] = p0*va.w + p1*wa.w;
            o[4] = p0*vb.x + p1*wb.x;  o[5] = p0*vb.y + p1*wb.y;
            o[6] = p0*vb.z + p1*wb.z;  o[7] = p0*vb.w + p1*wb.w;
#pragma unroll
            for (int e = 0; e < 8; e++) o[e] = warp_sum(o[e]);
            if (lane == 0) {
                float inv = 1.0f / sum;
#pragma unroll
                for (int e = 0; e < 8; e++) at[h*8 + e] = o[e] * inv;
            }
        }
        __syncthreads();

        if (t < 32) {
            float o = out_b[l*32 + t];
#pragma unroll
            for (int c = 0; c < 32; c++) o = fmaf(at[c], ow[t*33 + c], o);
            float val = xv[t] + o;
            float mean = warp_sum(val) * (1.0f/32.0f);
            float dvv = val - mean;
            float var = warp_sum(dvv*dvv) * (1.0f/32.0f);
            xs[t] = dvv * rsqrtf(var + 1e-5f) * ln1g[l*32 + t] + ln1b[l*32 + t];
        }
        __syncthreads();

        float4 xr[8];
#pragma unroll
        for (int i = 0; i < 8; i++) xr[i] = *(const float4*)(xs + i*4);
        const float* w1l = w1 + (size_t)l*1024*32;
        const float* b1l = b1 + l*1024;
#pragma unroll
        for (int i = 0; i < 4; i++) {
            int f = t*4 + i;
            float acc = b1l[f];
            const float4* wr = (const float4*)(w1l + (size_t)f*32);
#pragma unroll
            for (int d4 = 0; d4 < 8; d4++) {
                float4 w = wr[d4];
                float4 x = xr[d4];
                acc = fmaf(w.x, x.x, acc);
                acc = fmaf(w.y, x.y, acc);
                acc = fmaf(w.z, x.z, acc);
                acc = fmaf(w.w, x.w, acc);
            }
            gs[f] = 0.5f * acc * (1.0f + erff(acc * 0.70710678118654752f));
        }
        __syncthreads();
        const float* w2l = w2 + (size_t)l*32*1024;
#pragma unroll
        for (int pass = 0; pass < 4; pass++) {
            int d = pass*8 + wid;
            const float* wrow = w2l + (size_t)d*1024;
            float p = 0.f;
#pragma unroll 8
            for (int j = 0; j < 32; j++) p = fmaf(gs[j*32 + lane], wrow[j*32 + lane], p);
            p = warp_sum(p);
            if (lane == 0) ffo[d] = p;
        }
        __syncthreads();
        if (t < 32) {
            float val = xs[t] + ffo[t] + b2[l*32 + t];
            float mean = warp_sum(val) * (1.0f/32.0f);
            float dvv = val - mean;
            float var = warp_sum(dvv*dvv) * (1.0f/32.0f);
            xv[t] = dvv * rsqrtf(var + 1e-5f) * ln2g[l*32 + t] + ln2b[l*32 + t];
        }
        __syncthreads();
    }

    if (t < 32) {
        float y = xv[t];
        out[128 + tau*32 + t] = y;
        if (tau < 4) out[tau*32 + t] = y;
    }
}

// ---------------- launch ----------------
extern "C" void kernel_launch(void* const* d_in, const int* in_sizes, int n_in,
                              void* d_out, int out_size) {
    const float* v     = (const float*)d_in[0];
    const int*   edge  = (const int*)d_in[2];
    const float* W_emb = (const float*)d_in[3];
    const float* b_emb = (const float*)d_in[4];
    const float* W_g1  = (const float*)d_in[5];
    const float* b_g1  = (const float*)d_in[6];
    const float* W_g2  = (const float*)d_in[7];
    const float* b_g2  = (const float*)d_in[8];
    const float* W_fc  = (const float*)d_in[9];
    const float* b_fc  = (const float*)d_in[10];
    const float* muQ   = (const float*)d_in[11];
    const float* sigQ  = (const float*)d_in[12];
    const float* pe    = (const float*)d_in[13];
    const float* in_w  = (const float*)d_in[14];
    const float* in_b  = (const float*)d_in[15];
    const float* out_w = (const float*)d_in[16];
    const float* out_b = (const float*)d_in[17];
    const float* ln1g  = (const float*)d_in[18];
    const float* ln1b  = (const float*)d_in[19];
    const float* w1    = (const float*)d_in[20];
    const float* b1    = (const float*)d_in[21];
    const float* w2    = (const float*)d_in[22];
    const float* b2    = (const float*)d_in[23];
    const float* ln2g  = (const float*)d_in[24];
    const float* ln2b  = (const float*)d_in[25];

    k_prep<<<G_, 256>>>(edge, W_g2, W_g1);                       // 0
    k_nop<<<1, 32>>>();                                          // 1
    k_agg_gemm1<<<5000, 128>>>(v, W_emb, b_emb, b_g1);           // 2
    k_agg128<<<5000, 256>>>();                                   // 3 <- ncu capture slot
    k_mma_gemm2pool<<<NT_, 256>>>(b_g2);                         // 4
    k_fc<<<G_, 256>>>(W_fc, b_fc, pe, muQ, sigQ);                // 5
    k_transformer<<<NB_, 256>>>(in_w, in_b, out_w, out_b, ln1g, ln1b,
                                w1, b1, w2, b2, ln2g, ln2b, (float*)d_out);  // 6
}